// round 13
// baseline (speedup 1.0000x reference)
#include <cuda_runtime.h>
#include <cuda_fp16.h>
#include <math.h>
#include <stdint.h>

#define Bsz 2
#define Tt  2048
#define Cc  1024
#define Hh  16
#define KVh 4
#define HDim 64
#define QKVN 1536   // 1024 Q + 256 K + 256 V
#define QSCALE 0.1803368801111204f   // 0.125 * log2(e)

// -------- scratch (static device globals; no allocation) --------
__device__ __align__(256) __half g_Xh[Bsz * Tt * Cc];
__device__ __align__(256) __half g_QKVh[Bsz * Tt * QKVN];   // fp16, Q pre-scaled
__device__ __align__(256) __half g_Yh[Bsz * Tt * Hh * HDim];
__device__ __align__(256) __half g_WqkvTh[QKVN * Cc];
__device__ __align__(256) __half g_WoTh[Cc * Cc];

__device__ __forceinline__ void mma16816(float* c,
    uint32_t a0, uint32_t a1, uint32_t a2, uint32_t a3,
    uint32_t b0, uint32_t b1) {
    asm volatile(
        "mma.sync.aligned.m16n8k16.row.col.f32.f16.f16.f32 "
        "{%0,%1,%2,%3}, {%4,%5,%6,%7}, {%8,%9}, {%0,%1,%2,%3};"
        : "+f"(c[0]), "+f"(c[1]), "+f"(c[2]), "+f"(c[3])
        : "r"(a0), "r"(a1), "r"(a2), "r"(a3), "r"(b0), "r"(b1));
}

__device__ __forceinline__ void ldmx4(uint32_t* r, uint32_t saddr) {
    asm volatile("ldmatrix.sync.aligned.m8n8.x4.shared.b16 {%0,%1,%2,%3}, [%4];"
        : "=r"(r[0]), "=r"(r[1]), "=r"(r[2]), "=r"(r[3]) : "r"(saddr));
}
__device__ __forceinline__ void ldmx4t(uint32_t* r, uint32_t saddr) {
    asm volatile("ldmatrix.sync.aligned.m8n8.x4.trans.shared.b16 {%0,%1,%2,%3}, [%4];"
        : "=r"(r[0]), "=r"(r[1]), "=r"(r[2]), "=r"(r[3]) : "r"(saddr));
}

// .cg: bypass L1 (stream-once data); 16B only
__device__ __forceinline__ void cpa16(void* s, const void* g) {
    uint32_t sa = (uint32_t)__cvta_generic_to_shared(s);
    asm volatile("cp.async.cg.shared.global [%0], [%1], 16;" :: "r"(sa), "l"(g));
}
#define CP_COMMIT() asm volatile("cp.async.commit_group;" ::: "memory")
#define CP_WAIT(n)  asm volatile("cp.async.wait_group %0;" :: "n"(n) : "memory")

__device__ __forceinline__ float ex2f(float x) {
    float y;
    asm("ex2.approx.ftz.f32 %0, %1;" : "=f"(y) : "f"(x));
    return y;
}
__device__ __forceinline__ uint32_t packh2(float a, float b) {
    __half2 h = __floats2half2_rn(a, b);
    return *reinterpret_cast<uint32_t*>(&h);
}

// ============================================================
// Fused prep: cvt_x (blocks 0..4095), transpose_qkv
// (blocks 4096..5631), transpose Wo (blocks 5632..6655).
// ============================================================
#define PREP_CVT 4096
#define PREP_QKV 1536
#define PREP_WO  1024
#define PREP_GRID (PREP_CVT + PREP_QKV + PREP_WO)

__global__ __launch_bounds__(256) void prep(
    const float* __restrict__ x,
    const float* __restrict__ Wq, const float* __restrict__ Wk,
    const float* __restrict__ Wv, const float* __restrict__ Wo,
    __half* __restrict__ Xh, __half* __restrict__ WqkvTh,
    __half* __restrict__ WoTh)
{
    int blk = blockIdx.x;
    int tid = threadIdx.x;

    if (blk < PREP_CVT) {
        int i = blk * 256 + tid;
        float4 v = *(const float4*)(x + (size_t)i * 4);
        __half2* o = (__half2*)(Xh + (size_t)i * 4);
        o[0] = __floats2half2_rn(v.x, v.y);
        o[1] = __floats2half2_rn(v.z, v.w);
        return;
    }

    __shared__ float tile[32][33];
    int tx = tid & 31, ty = tid >> 5;
    const float* src;
    __half* dst;
    int N, nloc, k0, orow;

    if (blk < PREP_CVT + PREP_QKV) {
        int b = blk - PREP_CVT;
        int nblk = b % 48;
        k0 = (b / 48) * 32;
        if (nblk < 32)      { src = Wq; N = 1024; nloc = nblk * 32; }
        else if (nblk < 40) { src = Wk; N = 256;  nloc = (nblk - 32) * 32; }
        else                { src = Wv; N = 256;  nloc = (nblk - 40) * 32; }
        dst = WqkvTh; orow = nblk * 32;
    } else {
        int b = blk - PREP_CVT - PREP_QKV;
        src = Wo; N = 1024;
        nloc = (b % 32) * 32;
        k0 = (b / 32) * 32;
        dst = WoTh; orow = nloc;
    }

#pragma unroll
    for (int i = 0; i < 32; i += 8)
        tile[ty + i][tx] = src[(size_t)(k0 + ty + i) * N + nloc + tx];
    __syncthreads();
#pragma unroll
    for (int i = 0; i < 32; i += 8)
        dst[(size_t)(orow + ty + i) * Cc + k0 + tx] = __float2half(tile[tx][ty + i]);
}

// ============================================================
// GEMM common: 128 threads, 4 warps of 64x64 (CTA 128x128).
// ============================================================
#define SMH 40
#define STG_A (128 * SMH)
#define STAGE_H (2 * 128 * SMH)
#define GEMM_SMEM (3 * STAGE_H * 2)   // 61440 bytes

#define GEMM_MAINLOOP(Aptr, Bptr)                                              \
    float acc[4][8][4];                                                        \
    _Pragma("unroll") for (int mt = 0; mt < 4; mt++)                           \
    _Pragma("unroll") for (int nt = 0; nt < 8; nt++)                           \
    _Pragma("unroll") for (int i = 0; i < 4; i++) acc[mt][nt][i] = 0.f;        \
    auto issue = [&](int st, int kc) {                                         \
        __half* As = sh + st * STAGE_H;                                        \
        __half* Bs = As + STG_A;                                               \
        _Pragma("unroll") for (int i = 0; i < 4; i++) {                        \
            int row = i * 32 + crow;                                           \
            cpa16(&As[row * SMH + ccol], Aptr + (size_t)(bm + row) * 1024 + kc + ccol); \
            cpa16(&Bs[row * SMH + ccol], Bptr + (size_t)(bn + row) * 1024 + kc + ccol); \
        }                                                                      \
        CP_COMMIT();                                                           \
    };                                                                         \
    issue(0, 0);                                                               \
    issue(1, 32);                                                              \
    int s = 0;                                                                 \
    for (int c = 0; c < 32; c++) {                                             \
        if (c == 31) { CP_WAIT(0); } else { CP_WAIT(1); }                      \
        __syncthreads();                                                       \
        if (c + 2 < 32) {                                                      \
            int s2 = s + 2; if (s2 >= 3) s2 -= 3;                              \
            issue(s2, (c + 2) * 32);                                           \
        }                                                                      \
        uint32_t As_u = sh_u + s * STAGE_H * 2;                                \
        uint32_t Bs_u = As_u + STG_A * 2;                                      \
        _Pragma("unroll") for (int ks = 0; ks < 2; ks++) {                     \
            int k0 = ks * 16;                                                  \
            uint32_t am[4][4], bmx[4][4];                                      \
            _Pragma("unroll") for (int mt = 0; mt < 4; mt++)                   \
                ldmx4(am[mt], As_u + 2 * ((m0 + mt * 16 + aro) * SMH + k0 + aco)); \
            _Pragma("unroll") for (int p = 0; p < 4; p++)                      \
                ldmx4(bmx[p], Bs_u + 2 * ((n0 + p * 16 + bro) * SMH + k0 + bco)); \
            _Pragma("unroll") for (int mt = 0; mt < 4; mt++)                   \
            _Pragma("unroll") for (int p = 0; p < 4; p++) {                    \
                mma16816(acc[mt][2 * p],     am[mt][0], am[mt][1], am[mt][2], am[mt][3], \
                         bmx[p][0], bmx[p][1]);                                \
                mma16816(acc[mt][2 * p + 1], am[mt][0], am[mt][1], am[mt][2], am[mt][3], \
                         bmx[p][2], bmx[p][3]);                                \
            }                                                                  \
        }                                                                      \
        if (++s >= 3) s -= 3;                                                  \
    }

#define GEMM_PROLOG                                                            \
    extern __shared__ __half sh[];                                             \
    int tid = threadIdx.x, wid = tid >> 5, lane = tid & 31;                    \
    int gr = lane >> 2, gc = lane & 3;                                         \
    int bm = blockIdx.y * 128, bn = blockIdx.x * 128;                          \
    int m0 = (wid & 1) * 64, n0 = (wid >> 1) * 64;                             \
    const int aro = ((lane & 8) ? 8 : 0) + (lane & 7);                         \
    const int aco = (lane & 16) ? 8 : 0;                                       \
    const int bro = ((lane & 16) ? 8 : 0) + (lane & 7);                        \
    const int bco = (lane & 8) ? 8 : 0;                                        \
    const int crow = tid >> 2;                                                 \
    const int ccol = (tid & 3) * 8;                                            \
    const uint32_t sh_u = (uint32_t)__cvta_generic_to_shared(sh);

// ============================================================
// QKV GEMM + register-local rope/rms epilogue -> fp16 QKVh.
// ============================================================
__global__ __launch_bounds__(128, 3) void gemm_qkv(
    const __half* __restrict__ A, const __half* __restrict__ BT,
    __half* __restrict__ Og,
    const float* __restrict__ cosp, const float* __restrict__ sinp)
{
    GEMM_PROLOG
    GEMM_MAINLOOP(A, BT)

    int ntile = blockIdx.x;
    int hb = bn + n0;

    if (ntile >= 10) {
#pragma unroll
        for (int mt = 0; mt < 4; mt++)
#pragma unroll
            for (int nt = 0; nt < 8; nt++) {
                int row = bm + m0 + mt * 16 + gr;
                int col = hb + nt * 8 + 2 * gc;
                *(__half2*)&Og[(size_t)row * QKVN + col] =
                    __floats2half2_rn(acc[mt][nt][0], acc[mt][nt][1]);
                *(__half2*)&Og[(size_t)(row + 8) * QKVN + col] =
                    __floats2half2_rn(acc[mt][nt][2], acc[mt][nt][3]);
            }
        return;
    }

    float scl = (ntile < 8) ? QSCALE : 1.0f;
#pragma unroll
    for (int mt = 0; mt < 4; mt++) {
#pragma unroll
        for (int j = 0; j < 2; j++) {
            int row = bm + m0 + mt * 16 + gr + j * 8;
            int t = row & (Tt - 1);
            float o1a[4][2], o2a[4][2];
            float ss = 0.f;
#pragma unroll
            for (int nt = 0; nt < 4; nt++) {
                int d = nt * 8 + 2 * gc;
                float2 c2 = *(const float2*)&cosp[t * 32 + d];
                float2 s2 = *(const float2*)&sinp[t * 32 + d];
#pragma unroll
                for (int i = 0; i < 2; i++) {
                    float cv = i ? c2.y : c2.x;
                    float sv = i ? s2.y : s2.x;
                    float x1 = acc[mt][nt][j * 2 + i];
                    float x2 = acc[mt][nt + 4][j * 2 + i];
                    float o1 = x1 * cv + x2 * sv;
                    float o2 = -x1 * sv + x2 * cv;
                    o1a[nt][i] = o1;
                    o2a[nt][i] = o2;
                    ss += o1 * o1 + o2 * o2;
                }
            }
            ss += __shfl_xor_sync(0xffffffffu, ss, 1);
            ss += __shfl_xor_sync(0xffffffffu, ss, 2);
            float inv = rsqrtf(ss * (1.0f / HDim) + 1e-6f) * scl;

            __half* og = Og + (size_t)row * QKVN + hb;
#pragma unroll
            for (int nt = 0; nt < 4; nt++) {
                int d = nt * 8 + 2 * gc;
                *(__half2*)&og[d] =
                    __floats2half2_rn(o1a[nt][0] * inv, o1a[nt][1] * inv);
                *(__half2*)&og[d + 32] =
                    __floats2half2_rn(o2a[nt][0] * inv, o2a[nt][1] * inv);
            }
        }
    }
}

// ============================================================
// Wo GEMM: fp16 in, fp32 out.
// ============================================================
__global__ __launch_bounds__(128, 3) void gemm_wo(
    const __half* __restrict__ A, const __half* __restrict__ BT,
    float* __restrict__ C)
{
    GEMM_PROLOG
    GEMM_MAINLOOP(A, BT)

#pragma unroll
    for (int mt = 0; mt < 4; mt++)
#pragma unroll
        for (int nt = 0; nt < 8; nt++) {
            int row = bm + m0 + mt * 16 + gr;
            int col = bn + n0 + nt * 8 + 2 * gc;
            *(float2*)&C[(size_t)row * Cc + col] =
                make_float2(acc[mt][nt][0], acc[mt][nt][1]);
            *(float2*)&C[(size_t)(row + 8) * Cc + col] =
                make_float2(acc[mt][nt][2], acc[mt][nt][3]);
        }
}

// ============================================================
// fp16 flash attention: 256 threads, 8 warps x 16 q-rows,
// register-resident P, double-buffered KV, 4 warps/SMSP.
// ============================================================
#define AST 72
#define QS_OFF 0
#define KS_OFF (128 * AST)
#define VS_OFF (KS_OFF + 2 * 64 * AST)
#define FLASH_SMEM ((128 * AST + 4 * 64 * AST) * 2)   // 55296 bytes

__global__ __launch_bounds__(256, 2) void flash_attn_mma(
    const __half* __restrict__ QKV, __half* __restrict__ Og)
{
    extern __shared__ __half sm[];

    int qb = (gridDim.x - 1) - blockIdx.x;   // LPT: biggest first
    int h = blockIdx.y, b = blockIdx.z;
    int q0 = qb * 128;
    int kvh = h >> 2;
    int tid = threadIdx.x, wid = tid >> 5, lane = tid & 31;
    int gr = lane >> 2, gc = lane & 3;
    int m0 = wid * 16;
    const int aro = ((lane & 8) ? 8 : 0) + (lane & 7);
    const int aco = (lane & 16) ? 8 : 0;
    const int bro = ((lane & 16) ? 8 : 0) + (lane & 7);
    const int bco = (lane & 8) ? 8 : 0;

    const uint32_t sm_u = (uint32_t)__cvta_generic_to_shared(sm);
    const uint32_t Qs_u = sm_u + QS_OFF * 2;

    const __half* Qbase = QKV + (size_t)(b * Tt + q0) * QKVN + h * HDim;
    const __half* KVbase = QKV + (size_t)(b * Tt) * QKVN + 1024 + kvh * HDim;

    // ---- stage Q (fp16, pre-scaled) ----
#pragma unroll
    for (int i = 0; i < 4; i++) {
        int fi = i * 256 + tid;
        int row = fi >> 3, c8 = (fi & 7) * 8;
        cpa16(&sm[QS_OFF + row * AST + c8], Qbase + (size_t)row * QKVN + c8);
    }
    CP_COMMIT();

    auto issueKV = [&](int sbuf, int kt) {
        const __half* Kb = KVbase + (size_t)(kt * 64) * QKVN;
#pragma unroll
        for (int i = 0; i < 2; i++) {
            int fi = i * 256 + tid;
            int row = fi >> 3, c8 = (fi & 7) * 8;
            const __half* g = Kb + (size_t)row * QKVN + c8;
            cpa16(&sm[KS_OFF + sbuf * 64 * AST + row * AST + c8], g);
            cpa16(&sm[VS_OFF + sbuf * 64 * AST + row * AST + c8], g + 256);
        }
        CP_COMMIT();
    };

    issueKV(0, 0);
    CP_WAIT(1);
    __syncthreads();

    // ---- Q fragments ----
    uint32_t qf[4][4];
#pragma unroll
    for (int ks = 0; ks < 4; ks++)
        ldmx4(qf[ks], Qs_u + 2 * ((m0 + aro) * AST + ks * 16 + aco));

    float o[8][4];
#pragma unroll
    for (int nt = 0; nt < 8; nt++)
#pragma unroll
        for (int i = 0; i < 4; i++) o[nt][i] = 0.f;
    float m_lo = -1e30f, m_hi = -1e30f, l_lo = 0.f, l_hi = 0.f;

    const int row_lo = q0 + m0 + gr;
    const int row_hi = row_lo + 8;
    const int nkt = 2 * qb + 2;

    for (int kt = 0; kt < nkt; kt++) {
        int kv0 = kt * 64;
        int buf = kt & 1;
        CP_WAIT(0);
        __syncthreads();
        if (kt + 1 < nkt) issueKV(buf ^ 1, kt + 1);

        uint32_t Ks_u = sm_u + (KS_OFF + buf * 64 * AST) * 2;
        uint32_t Vs_u = sm_u + (VS_OFF + buf * 64 * AST) * 2;

        // ---- S = Q K^T ----
        float s[8][4];
#pragma unroll
        for (int nt = 0; nt < 8; nt++)
#pragma unroll
            for (int i = 0; i < 4; i++) s[nt][i] = 0.f;

#pragma unroll
        for (int ks = 0; ks < 4; ks++) {
            uint32_t kf[4][4];
#pragma unroll
            for (int p = 0; p < 4; p++)
                ldmx4(kf[p], Ks_u + 2 * ((p * 16 + bro) * AST + ks * 16 + bco));
#pragma unroll
            for (int nt = 0; nt < 8; nt++) {
                int p = nt >> 1, hh = nt & 1;
                mma16816(s[nt], qf[ks][0], qf[ks][1], qf[ks][2], qf[ks][3],
                         kf[p][2 * hh], kf[p][2 * hh + 1]);
            }
        }

        // ---- causal mask (diagonal region only) ----
        if (kv0 + 63 > q0) {
#pragma unroll
            for (int nt = 0; nt < 8; nt++) {
                int c0 = kv0 + nt * 8 + 2 * gc;
                if (c0 > row_lo)     s[nt][0] = -1e30f;
                if (c0 + 1 > row_lo) s[nt][1] = -1e30f;
                if (c0 > row_hi)     s[nt][2] = -1e30f;
                if (c0 + 1 > row_hi) s[nt][3] = -1e30f;
            }
        }

        // ---- online softmax + register-resident P ----
        float tlo = -1e30f, thi = -1e30f;
#pragma unroll
        for (int nt = 0; nt < 8; nt++) {
            tlo = fmaxf(tlo, fmaxf(s[nt][0], s[nt][1]));
            thi = fmaxf(thi, fmaxf(s[nt][2], s[nt][3]));
        }
        tlo = fmaxf(tlo, __shfl_xor_sync(0xffffffffu, tlo, 1));
        tlo = fmaxf(tlo, __shfl_xor_sync(0xffffffffu, tlo, 2));
        thi = fmaxf(thi, __shfl_xor_sync(0xffffffffu, thi, 1));
        thi = fmaxf(thi, __shfl_xor_sync(0xffffffffu, thi, 2));

        float mn_lo = fmaxf(m_lo, tlo);
        float mn_hi = fmaxf(m_hi, thi);
        float cor_lo = ex2f(m_lo - mn_lo);
        float cor_hi = ex2f(m_hi - mn_hi);
        m_lo = mn_lo; m_hi = mn_hi;
        l_lo *= cor_lo; l_hi *= cor_hi;
#pragma unroll
        for (int nt = 0; nt < 8; nt++) {
            o[nt][0] *= cor_lo; o[nt][1] *= cor_lo;
            o[nt][2] *= cor_hi; o[nt][3] *= cor_hi;
        }

        uint32_t pf[4][4];
#pragma unroll
        for (int ks = 0; ks < 4; ks++) {
            float a0 = ex2f(s[2 * ks][0] - mn_lo);
            float a1 = ex2f(s[2 * ks][1] - mn_lo);
            float a2 = ex2f(s[2 * ks][2] - mn_hi);
            float a3 = ex2f(s[2 * ks][3] - mn_hi);
            float b0 = ex2f(s[2 * ks + 1][0] - mn_lo);
            float b1 = ex2f(s[2 * ks + 1][1] - mn_lo);
            float b2 = ex2f(s[2 * ks + 1][2] - mn_hi);
            float b3 = ex2f(s[2 * ks + 1][3] - mn_hi);
            l_lo += a0 + a1 + b0 + b1;
            l_hi += a2 + a3 + b2 + b3;
            pf[ks][0] = packh2(a0, a1);
            pf[ks][1] = packh2(a2, a3);
            pf[ks][2] = packh2(b0, b1);
            pf[ks][3] = packh2(b2, b3);
        }

        // ---- O += P V ----
#pragma unroll
        for (int ks = 0; ks < 4; ks++) {
            uint32_t vf[4][4];
#pragma unroll
            for (int p = 0; p < 4; p++)
                ldmx4t(vf[p], Vs_u + 2 * ((ks * 16 + aro) * AST + p * 16 + aco));
#pragma unroll
            for (int nt = 0; nt < 8; nt++) {
                int p = nt >> 1, hh = nt & 1;
                mma16816(o[nt], pf[ks][0], pf[ks][1], pf[ks][2], pf[ks][3],
                         vf[p][2 * hh], vf[p][2 * hh + 1]);
            }
        }
    }

    // ---- finalize ----
    l_lo += __shfl_xor_sync(0xffffffffu, l_lo, 1);
    l_lo += __shfl_xor_sync(0xffffffffu, l_lo, 2);
    l_hi += __shfl_xor_sync(0xffffffffu, l_hi, 1);
    l_hi += __shfl_xor_sync(0xffffffffu, l_hi, 2);
    float inv_lo = 1.f / l_lo;
    float inv_hi = 1.f / l_hi;

    __half* Obase = Og + ((size_t)(b * Tt) * Hh + h) * HDim;
#pragma unroll
    for (int nt = 0; nt < 8; nt++) {
        int col = nt * 8 + 2 * gc;
        *(__half2*)&Obase[(size_t)row_lo * (Hh * HDim) + col] =
            __floats2half2_rn(o[nt][0] * inv_lo, o[nt][1] * inv_lo);
        *(__half2*)&Obase[(size_t)row_hi * (Hh * HDim) + col] =
            __floats2half2_rn(o[nt][2] * inv_hi, o[nt][3] * inv_hi);
    }
}

// ============================================================
// launch
// ============================================================
extern "C" void kernel_launch(void* const* d_in, const int* in_sizes, int n_in,
                              void* d_out, int out_size)
{
    const float* x  = (const float*)d_in[0];
    const float* cs = (const float*)d_in[1];
    const float* sn = (const float*)d_in[2];
    const float* Wq = (const float*)d_in[3];
    const float* Wk = (const float*)d_in[4];
    const float* Wv = (const float*)d_in[5];
    const float* Wo = (const float*)d_in[6];
    float* out = (float*)d_out;

    __half *Xh, *QKVh, *Yh, *WqkvTh, *WoTh;
    cudaGetSymbolAddress((void**)&Xh, g_Xh);
    cudaGetSymbolAddress((void**)&QKVh, g_QKVh);
    cudaGetSymbolAddress((void**)&Yh, g_Yh);
    cudaGetSymbolAddress((void**)&WqkvTh, g_WqkvTh);
    cudaGetSymbolAddress((void**)&WoTh, g_WoTh);

    cudaFuncSetAttribute(gemm_qkv,
                         cudaFuncAttributeMaxDynamicSharedMemorySize, GEMM_SMEM);
    cudaFuncSetAttribute(gemm_wo,
                         cudaFuncAttributeMaxDynamicSharedMemorySize, GEMM_SMEM);
    cudaFuncSetAttribute(flash_attn_mma,
                         cudaFuncAttributeMaxDynamicSharedMemorySize, FLASH_SMEM);

    const int M = Bsz * Tt;  // 4096

    // fused prep: x->fp16 + both weight transposes in one launch
    prep<<<PREP_GRID, 256>>>(x, Wq, Wk, Wv, Wo, Xh, WqkvTh, WoTh);

    // fused QKV projection + rope + rms -> fp16 (Q pre-scaled)
    gemm_qkv<<<dim3(QKVN / 128, M / 128), 128, GEMM_SMEM>>>(Xh, WqkvTh, QKVh, cs, sn);

    // causal GQA flash attention (256 thr, register-resident P)
    flash_attn_mma<<<dim3(Tt / 128, Hh, Bsz), 256, FLASH_SMEM>>>(QKVh, Yh);

    // output projection
    gemm_wo<<<dim3(Cc / 128, M / 128), 128, GEMM_SMEM>>>(Yh, WoTh, out);
}

// round 14
// speedup vs baseline: 1.1074x; 1.1074x over previous
#include <cuda_runtime.h>
#include <cuda_fp16.h>
#include <math.h>
#include <stdint.h>

#define Bsz 2
#define Tt  2048
#define Cc  1024
#define Hh  16
#define KVh 4
#define HDim 64
#define QKVN 1536   // 1024 Q + 256 K + 256 V
#define QSCALE 0.1803368801111204f   // 0.125 * log2(e)

// -------- scratch (static device globals; no allocation) --------
__device__ __align__(256) __half g_Xh[Bsz * Tt * Cc];
__device__ __align__(256) __half g_QKVh[Bsz * Tt * QKVN];   // fp16, Q pre-scaled
__device__ __align__(256) __half g_Yh[Bsz * Tt * Hh * HDim];
__device__ __align__(256) __half g_WqkvTh[QKVN * Cc];
__device__ __align__(256) __half g_WoTh[Cc * Cc];

__device__ __forceinline__ void mma16816(float* c,
    uint32_t a0, uint32_t a1, uint32_t a2, uint32_t a3,
    uint32_t b0, uint32_t b1) {
    asm volatile(
        "mma.sync.aligned.m16n8k16.row.col.f32.f16.f16.f32 "
        "{%0,%1,%2,%3}, {%4,%5,%6,%7}, {%8,%9}, {%0,%1,%2,%3};"
        : "+f"(c[0]), "+f"(c[1]), "+f"(c[2]), "+f"(c[3])
        : "r"(a0), "r"(a1), "r"(a2), "r"(a3), "r"(b0), "r"(b1));
}

__device__ __forceinline__ void ldmx4(uint32_t* r, uint32_t saddr) {
    asm volatile("ldmatrix.sync.aligned.m8n8.x4.shared.b16 {%0,%1,%2,%3}, [%4];"
        : "=r"(r[0]), "=r"(r[1]), "=r"(r[2]), "=r"(r[3]) : "r"(saddr));
}
__device__ __forceinline__ void ldmx4t(uint32_t* r, uint32_t saddr) {
    asm volatile("ldmatrix.sync.aligned.m8n8.x4.trans.shared.b16 {%0,%1,%2,%3}, [%4];"
        : "=r"(r[0]), "=r"(r[1]), "=r"(r[2]), "=r"(r[3]) : "r"(saddr));
}

__device__ __forceinline__ void cpa16(void* s, const void* g) {
    uint32_t sa = (uint32_t)__cvta_generic_to_shared(s);
    asm volatile("cp.async.ca.shared.global [%0], [%1], 16;" :: "r"(sa), "l"(g));
}
#define CP_COMMIT() asm volatile("cp.async.commit_group;" ::: "memory")
#define CP_WAIT(n)  asm volatile("cp.async.wait_group %0;" :: "n"(n) : "memory")

__device__ __forceinline__ float ex2f(float x) {
    float y;
    asm("ex2.approx.ftz.f32 %0, %1;" : "=f"(y) : "f"(x));
    return y;
}
__device__ __forceinline__ uint32_t packh2(float a, float b) {
    __half2 h = __floats2half2_rn(a, b);
    return *reinterpret_cast<uint32_t*>(&h);
}

// ============================================================
// Fused prep: cvt_x (blocks 0..2047, 32B/thread),
// transpose_qkv (next 1536), transpose Wo (next 1024).
// ============================================================
#define PREP_CVT 2048
#define PREP_QKV 1536
#define PREP_WO  1024
#define PREP_GRID (PREP_CVT + PREP_QKV + PREP_WO)

__global__ __launch_bounds__(256) void prep(
    const float* __restrict__ x,
    const float* __restrict__ Wq, const float* __restrict__ Wk,
    const float* __restrict__ Wv, const float* __restrict__ Wo,
    __half* __restrict__ Xh, __half* __restrict__ WqkvTh,
    __half* __restrict__ WoTh)
{
    int blk = blockIdx.x;
    int tid = threadIdx.x;

    if (blk < PREP_CVT) {
        size_t i = ((size_t)blk * 256 + tid) * 8;
        float4 v0 = *(const float4*)(x + i);
        float4 v1 = *(const float4*)(x + i + 4);
        __half2* o = (__half2*)(Xh + i);
        o[0] = __floats2half2_rn(v0.x, v0.y);
        o[1] = __floats2half2_rn(v0.z, v0.w);
        o[2] = __floats2half2_rn(v1.x, v1.y);
        o[3] = __floats2half2_rn(v1.z, v1.w);
        return;
    }

    __shared__ float tile[32][33];
    int tx = tid & 31, ty = tid >> 5;
    const float* src;
    __half* dst;
    int N, nloc, k0, orow;

    if (blk < PREP_CVT + PREP_QKV) {
        int b = blk - PREP_CVT;
        int nblk = b % 48;
        k0 = (b / 48) * 32;
        if (nblk < 32)      { src = Wq; N = 1024; nloc = nblk * 32; }
        else if (nblk < 40) { src = Wk; N = 256;  nloc = (nblk - 32) * 32; }
        else                { src = Wv; N = 256;  nloc = (nblk - 40) * 32; }
        dst = WqkvTh; orow = nblk * 32;
    } else {
        int b = blk - PREP_CVT - PREP_QKV;
        src = Wo; N = 1024;
        nloc = (b % 32) * 32;
        k0 = (b / 32) * 32;
        dst = WoTh; orow = nloc;
    }

#pragma unroll
    for (int i = 0; i < 32; i += 8)
        tile[ty + i][tx] = src[(size_t)(k0 + ty + i) * N + nloc + tx];
    __syncthreads();
#pragma unroll
    for (int i = 0; i < 32; i += 8)
        dst[(size_t)(orow + ty + i) * Cc + k0 + tx] = __float2half(tile[tx][ty + i]);
}

// ============================================================
// GEMM common: 128 threads, 4 warps of 64x64 (CTA 128x128).
// ============================================================
#define SMH 40
#define STG_A (128 * SMH)
#define STAGE_H (2 * 128 * SMH)
#define GEMM_SMEM (3 * STAGE_H * 2)   // 61440 bytes

#define GEMM_MAINLOOP(Aptr, Bptr)                                              \
    float acc[4][8][4];                                                        \
    _Pragma("unroll") for (int mt = 0; mt < 4; mt++)                           \
    _Pragma("unroll") for (int nt = 0; nt < 8; nt++)                           \
    _Pragma("unroll") for (int i = 0; i < 4; i++) acc[mt][nt][i] = 0.f;        \
    auto issue = [&](int st, int kc) {                                         \
        __half* As = sh + st * STAGE_H;                                        \
        __half* Bs = As + STG_A;                                               \
        _Pragma("unroll") for (int i = 0; i < 4; i++) {                        \
            int row = i * 32 + crow;                                           \
            cpa16(&As[row * SMH + ccol], Aptr + (size_t)(bm + row) * 1024 + kc + ccol); \
            cpa16(&Bs[row * SMH + ccol], Bptr + (size_t)(bn + row) * 1024 + kc + ccol); \
        }                                                                      \
        CP_COMMIT();                                                           \
    };                                                                         \
    issue(0, 0);                                                               \
    issue(1, 32);                                                              \
    int s = 0;                                                                 \
    for (int c = 0; c < 32; c++) {                                             \
        if (c == 31) { CP_WAIT(0); } else { CP_WAIT(1); }                      \
        __syncthreads();                                                       \
        if (c + 2 < 32) {                                                      \
            int s2 = s + 2; if (s2 >= 3) s2 -= 3;                              \
            issue(s2, (c + 2) * 32);                                           \
        }                                                                      \
        uint32_t As_u = sh_u + s * STAGE_H * 2;                                \
        uint32_t Bs_u = As_u + STG_A * 2;                                      \
        _Pragma("unroll") for (int ks = 0; ks < 2; ks++) {                     \
            int k0 = ks * 16;                                                  \
            uint32_t am[4][4], bmx[4][4];                                      \
            _Pragma("unroll") for (int mt = 0; mt < 4; mt++)                   \
                ldmx4(am[mt], As_u + 2 * ((m0 + mt * 16 + aro) * SMH + k0 + aco)); \
            _Pragma("unroll") for (int p = 0; p < 4; p++)                      \
                ldmx4(bmx[p], Bs_u + 2 * ((n0 + p * 16 + bro) * SMH + k0 + bco)); \
            _Pragma("unroll") for (int mt = 0; mt < 4; mt++)                   \
            _Pragma("unroll") for (int p = 0; p < 4; p++) {                    \
                mma16816(acc[mt][2 * p],     am[mt][0], am[mt][1], am[mt][2], am[mt][3], \
                         bmx[p][0], bmx[p][1]);                                \
                mma16816(acc[mt][2 * p + 1], am[mt][0], am[mt][1], am[mt][2], am[mt][3], \
                         bmx[p][2], bmx[p][3]);                                \
            }                                                                  \
        }                                                                      \
        if (++s >= 3) s -= 3;                                                  \
    }

#define GEMM_PROLOG                                                            \
    extern __shared__ __half sh[];                                             \
    int tid = threadIdx.x, wid = tid >> 5, lane = tid & 31;                    \
    int gr = lane >> 2, gc = lane & 3;                                         \
    int bm = blockIdx.y * 128, bn = blockIdx.x * 128;                          \
    int m0 = (wid & 1) * 64, n0 = (wid >> 1) * 64;                             \
    const int aro = ((lane & 8) ? 8 : 0) + (lane & 7);                         \
    const int aco = (lane & 16) ? 8 : 0;                                       \
    const int bro = ((lane & 16) ? 8 : 0) + (lane & 7);                        \
    const int bco = (lane & 8) ? 8 : 0;                                        \
    const int crow = tid >> 2;                                                 \
    const int ccol = (tid & 3) * 8;                                            \
    const uint32_t sh_u = (uint32_t)__cvta_generic_to_shared(sh);

// ============================================================
// QKV GEMM + register-local rope/rms epilogue -> fp16 QKVh.
// ============================================================
__global__ __launch_bounds__(128, 3) void gemm_qkv(
    const __half* __restrict__ A, const __half* __restrict__ BT,
    __half* __restrict__ Og,
    const float* __restrict__ cosp, const float* __restrict__ sinp)
{
    GEMM_PROLOG
    GEMM_MAINLOOP(A, BT)

    int ntile = blockIdx.x;
    int hb = bn + n0;

    if (ntile >= 10) {
#pragma unroll
        for (int mt = 0; mt < 4; mt++)
#pragma unroll
            for (int nt = 0; nt < 8; nt++) {
                int row = bm + m0 + mt * 16 + gr;
                int col = hb + nt * 8 + 2 * gc;
                *(__half2*)&Og[(size_t)row * QKVN + col] =
                    __floats2half2_rn(acc[mt][nt][0], acc[mt][nt][1]);
                *(__half2*)&Og[(size_t)(row + 8) * QKVN + col] =
                    __floats2half2_rn(acc[mt][nt][2], acc[mt][nt][3]);
            }
        return;
    }

    float scl = (ntile < 8) ? QSCALE : 1.0f;
#pragma unroll
    for (int mt = 0; mt < 4; mt++) {
#pragma unroll
        for (int j = 0; j < 2; j++) {
            int row = bm + m0 + mt * 16 + gr + j * 8;
            int t = row & (Tt - 1);
            float o1a[4][2], o2a[4][2];
            float ss = 0.f;
#pragma unroll
            for (int nt = 0; nt < 4; nt++) {
                int d = nt * 8 + 2 * gc;
                float2 c2 = *(const float2*)&cosp[t * 32 + d];
                float2 s2 = *(const float2*)&sinp[t * 32 + d];
#pragma unroll
                for (int i = 0; i < 2; i++) {
                    float cv = i ? c2.y : c2.x;
                    float sv = i ? s2.y : s2.x;
                    float x1 = acc[mt][nt][j * 2 + i];
                    float x2 = acc[mt][nt + 4][j * 2 + i];
                    float o1 = x1 * cv + x2 * sv;
                    float o2 = -x1 * sv + x2 * cv;
                    o1a[nt][i] = o1;
                    o2a[nt][i] = o2;
                    ss += o1 * o1 + o2 * o2;
                }
            }
            ss += __shfl_xor_sync(0xffffffffu, ss, 1);
            ss += __shfl_xor_sync(0xffffffffu, ss, 2);
            float inv = rsqrtf(ss * (1.0f / HDim) + 1e-6f) * scl;

            __half* og = Og + (size_t)row * QKVN + hb;
#pragma unroll
            for (int nt = 0; nt < 4; nt++) {
                int d = nt * 8 + 2 * gc;
                *(__half2*)&og[d] =
                    __floats2half2_rn(o1a[nt][0] * inv, o1a[nt][1] * inv);
                *(__half2*)&og[d + 32] =
                    __floats2half2_rn(o2a[nt][0] * inv, o2a[nt][1] * inv);
            }
        }
    }
}

// ============================================================
// Wo GEMM: fp16 in, fp32 out.
// ============================================================
__global__ __launch_bounds__(128, 3) void gemm_wo(
    const __half* __restrict__ A, const __half* __restrict__ BT,
    float* __restrict__ C)
{
    GEMM_PROLOG
    GEMM_MAINLOOP(A, BT)

#pragma unroll
    for (int mt = 0; mt < 4; mt++)
#pragma unroll
        for (int nt = 0; nt < 8; nt++) {
            int row = bm + m0 + mt * 16 + gr;
            int col = bn + n0 + nt * 8 + 2 * gc;
            *(float2*)&C[(size_t)row * Cc + col] =
                make_float2(acc[mt][nt][0], acc[mt][nt][1]);
            *(float2*)&C[(size_t)(row + 8) * Cc + col] =
                make_float2(acc[mt][nt][2], acc[mt][nt][3]);
        }
}

// ============================================================
// fp16 flash attention: 128 threads, 4 warps x 32 q-rows,
// register-resident P, double-buffered KV, 1 barrier per tile.
// (R12 configuration — byte-optimal fragment amortization)
// ============================================================
#define AST 72
#define QS_OFF 0
#define KS_OFF (128 * AST)
#define VS_OFF (KS_OFF + 2 * 64 * AST)
#define FLASH_SMEM ((128 * AST + 4 * 64 * AST) * 2)   // 55296 bytes

__global__ __launch_bounds__(128) void flash_attn_mma(
    const __half* __restrict__ QKV, __half* __restrict__ Og)
{
    extern __shared__ __half sm[];

    int qb = (gridDim.x - 1) - blockIdx.x;   // LPT: biggest first
    int h = blockIdx.y, b = blockIdx.z;
    int q0 = qb * 128;
    int kvh = h >> 2;
    int tid = threadIdx.x, wid = tid >> 5, lane = tid & 31;
    int gr = lane >> 2, gc = lane & 3;
    int m0 = wid * 32;
    const int aro = ((lane & 8) ? 8 : 0) + (lane & 7);
    const int aco = (lane & 16) ? 8 : 0;
    const int bro = ((lane & 16) ? 8 : 0) + (lane & 7);
    const int bco = (lane & 8) ? 8 : 0;

    const uint32_t sm_u = (uint32_t)__cvta_generic_to_shared(sm);
    const uint32_t Qs_u = sm_u + QS_OFF * 2;

    const __half* Qbase = QKV + (size_t)(b * Tt + q0) * QKVN + h * HDim;
    const __half* KVbase = QKV + (size_t)(b * Tt) * QKVN + 1024 + kvh * HDim;

#pragma unroll
    for (int i = 0; i < 8; i++) {
        int fi = i * 128 + tid;
        int row = fi >> 3, c8 = (fi & 7) * 8;
        cpa16(&sm[QS_OFF + row * AST + c8], Qbase + (size_t)row * QKVN + c8);
    }
    CP_COMMIT();

    auto issueKV = [&](int sbuf, int kt) {
        const __half* Kb = KVbase + (size_t)(kt * 64) * QKVN;
#pragma unroll
        for (int i = 0; i < 4; i++) {
            int fi = i * 128 + tid;
            int row = fi >> 3, c8 = (fi & 7) * 8;
            const __half* g = Kb + (size_t)row * QKVN + c8;
            cpa16(&sm[KS_OFF + sbuf * 64 * AST + row * AST + c8], g);
            cpa16(&sm[VS_OFF + sbuf * 64 * AST + row * AST + c8], g + 256);
        }
        CP_COMMIT();
    };

    issueKV(0, 0);
    CP_WAIT(1);
    __syncthreads();

    uint32_t qf[2][4][4];
#pragma unroll
    for (int mt = 0; mt < 2; mt++)
#pragma unroll
        for (int ks = 0; ks < 4; ks++)
            ldmx4(qf[mt][ks], Qs_u + 2 * ((m0 + mt * 16 + aro) * AST + ks * 16 + aco));

    float o[2][8][4];
#pragma unroll
    for (int mt = 0; mt < 2; mt++)
#pragma unroll
        for (int nt = 0; nt < 8; nt++)
#pragma unroll
            for (int i = 0; i < 4; i++) o[mt][nt][i] = 0.f;
    float mx[2][2], lsum[2][2];
#pragma unroll
    for (int mt = 0; mt < 2; mt++) {
        mx[mt][0] = -1e30f; mx[mt][1] = -1e30f;
        lsum[mt][0] = 0.f;  lsum[mt][1] = 0.f;
    }

    const int nkt = 2 * qb + 2;

    for (int kt = 0; kt < nkt; kt++) {
        int kv0 = kt * 64;
        int buf = kt & 1;
        CP_WAIT(0);
        __syncthreads();
        if (kt + 1 < nkt) issueKV(buf ^ 1, kt + 1);

        uint32_t Ks_u = sm_u + (KS_OFF + buf * 64 * AST) * 2;
        uint32_t Vs_u = sm_u + (VS_OFF + buf * 64 * AST) * 2;

        float s[2][8][4];
#pragma unroll
        for (int mt = 0; mt < 2; mt++)
#pragma unroll
            for (int nt = 0; nt < 8; nt++)
#pragma unroll
                for (int i = 0; i < 4; i++) s[mt][nt][i] = 0.f;

#pragma unroll
        for (int ks = 0; ks < 4; ks++) {
            uint32_t kf[4][4];
#pragma unroll
            for (int p = 0; p < 4; p++)
                ldmx4(kf[p], Ks_u + 2 * ((p * 16 + bro) * AST + ks * 16 + bco));
#pragma unroll
            for (int mt = 0; mt < 2; mt++)
#pragma unroll
                for (int nt = 0; nt < 8; nt++) {
                    int p = nt >> 1, hh = nt & 1;
                    mma16816(s[mt][nt],
                             qf[mt][ks][0], qf[mt][ks][1], qf[mt][ks][2], qf[mt][ks][3],
                             kf[p][2 * hh], kf[p][2 * hh + 1]);
                }
        }

        if (kv0 + 63 > q0) {
#pragma unroll
            for (int mt = 0; mt < 2; mt++) {
                int rl = q0 + m0 + mt * 16 + gr;
                int rh = rl + 8;
#pragma unroll
                for (int nt = 0; nt < 8; nt++) {
                    int c0 = kv0 + nt * 8 + 2 * gc;
                    if (c0 > rl)     s[mt][nt][0] = -1e30f;
                    if (c0 + 1 > rl) s[mt][nt][1] = -1e30f;
                    if (c0 > rh)     s[mt][nt][2] = -1e30f;
                    if (c0 + 1 > rh) s[mt][nt][3] = -1e30f;
                }
            }
        }

        uint32_t pf[2][4][4];
#pragma unroll
        for (int mt = 0; mt < 2; mt++) {
            float tlo = -1e30f, thi = -1e30f;
#pragma unroll
            for (int nt = 0; nt < 8; nt++) {
                tlo = fmaxf(tlo, fmaxf(s[mt][nt][0], s[mt][nt][1]));
                thi = fmaxf(thi, fmaxf(s[mt][nt][2], s[mt][nt][3]));
            }
            tlo = fmaxf(tlo, __shfl_xor_sync(0xffffffffu, tlo, 1));
            tlo = fmaxf(tlo, __shfl_xor_sync(0xffffffffu, tlo, 2));
            thi = fmaxf(thi, __shfl_xor_sync(0xffffffffu, thi, 1));
            thi = fmaxf(thi, __shfl_xor_sync(0xffffffffu, thi, 2));

            float mn_lo = fmaxf(mx[mt][0], tlo);
            float mn_hi = fmaxf(mx[mt][1], thi);
            float cor_lo = ex2f(mx[mt][0] - mn_lo);
            float cor_hi = ex2f(mx[mt][1] - mn_hi);
            mx[mt][0] = mn_lo; mx[mt][1] = mn_hi;
            lsum[mt][0] *= cor_lo; lsum[mt][1] *= cor_hi;
#pragma unroll
            for (int nt = 0; nt < 8; nt++) {
                o[mt][nt][0] *= cor_lo; o[mt][nt][1] *= cor_lo;
                o[mt][nt][2] *= cor_hi; o[mt][nt][3] *= cor_hi;
            }

#pragma unroll
            for (int ks = 0; ks < 4; ks++) {
                float a0 = ex2f(s[mt][2 * ks][0] - mn_lo);
                float a1 = ex2f(s[mt][2 * ks][1] - mn_lo);
                float a2 = ex2f(s[mt][2 * ks][2] - mn_hi);
                float a3 = ex2f(s[mt][2 * ks][3] - mn_hi);
                float b0 = ex2f(s[mt][2 * ks + 1][0] - mn_lo);
                float b1 = ex2f(s[mt][2 * ks + 1][1] - mn_lo);
                float b2 = ex2f(s[mt][2 * ks + 1][2] - mn_hi);
                float b3 = ex2f(s[mt][2 * ks + 1][3] - mn_hi);
                lsum[mt][0] += a0 + a1 + b0 + b1;
                lsum[mt][1] += a2 + a3 + b2 + b3;
                pf[mt][ks][0] = packh2(a0, a1);
                pf[mt][ks][1] = packh2(a2, a3);
                pf[mt][ks][2] = packh2(b0, b1);
                pf[mt][ks][3] = packh2(b2, b3);
            }
        }

#pragma unroll
        for (int ks = 0; ks < 4; ks++) {
            uint32_t vf[4][4];
#pragma unroll
            for (int p = 0; p < 4; p++)
                ldmx4t(vf[p], Vs_u + 2 * ((ks * 16 + aro) * AST + p * 16 + aco));
#pragma unroll
            for (int mt = 0; mt < 2; mt++)
#pragma unroll
                for (int nt = 0; nt < 8; nt++) {
                    int p = nt >> 1, hh = nt & 1;
                    mma16816(o[mt][nt],
                             pf[mt][ks][0], pf[mt][ks][1], pf[mt][ks][2], pf[mt][ks][3],
                             vf[p][2 * hh], vf[p][2 * hh + 1]);
                }
        }
    }

    __half* Obase = Og + ((size_t)(b * Tt) * Hh + h) * HDim;
#pragma unroll
    for (int mt = 0; mt < 2; mt++) {
        float llo = lsum[mt][0], lhi = lsum[mt][1];
        llo += __shfl_xor_sync(0xffffffffu, llo, 1);
        llo += __shfl_xor_sync(0xffffffffu, llo, 2);
        lhi += __shfl_xor_sync(0xffffffffu, lhi, 1);
        lhi += __shfl_xor_sync(0xffffffffu, lhi, 2);
        float inv_lo = 1.f / llo;
        float inv_hi = 1.f / lhi;

        int row_lo = q0 + m0 + mt * 16 + gr;
        int row_hi = row_lo + 8;
#pragma unroll
        for (int nt = 0; nt < 8; nt++) {
            int col = nt * 8 + 2 * gc;
            *(__half2*)&Obase[(size_t)row_lo * (Hh * HDim) + col] =
                __floats2half2_rn(o[mt][nt][0] * inv_lo, o[mt][nt][1] * inv_lo);
            *(__half2*)&Obase[(size_t)row_hi * (Hh * HDim) + col] =
                __floats2half2_rn(o[mt][nt][2] * inv_hi, o[mt][nt][3] * inv_hi);
        }
    }
}

// ============================================================
// launch
// ============================================================
extern "C" void kernel_launch(void* const* d_in, const int* in_sizes, int n_in,
                              void* d_out, int out_size)
{
    const float* x  = (const float*)d_in[0];
    const float* cs = (const float*)d_in[1];
    const float* sn = (const float*)d_in[2];
    const float* Wq = (const float*)d_in[3];
    const float* Wk = (const float*)d_in[4];
    const float* Wv = (const float*)d_in[5];
    const float* Wo = (const float*)d_in[6];
    float* out = (float*)d_out;

    __half *Xh, *QKVh, *Yh, *WqkvTh, *WoTh;
    cudaGetSymbolAddress((void**)&Xh, g_Xh);
    cudaGetSymbolAddress((void**)&QKVh, g_QKVh);
    cudaGetSymbolAddress((void**)&Yh, g_Yh);
    cudaGetSymbolAddress((void**)&WqkvTh, g_WqkvTh);
    cudaGetSymbolAddress((void**)&WoTh, g_WoTh);

    cudaFuncSetAttribute(gemm_qkv,
                         cudaFuncAttributeMaxDynamicSharedMemorySize, GEMM_SMEM);
    cudaFuncSetAttribute(gemm_wo,
                         cudaFuncAttributeMaxDynamicSharedMemorySize, GEMM_SMEM);
    cudaFuncSetAttribute(flash_attn_mma,
                         cudaFuncAttributeMaxDynamicSharedMemorySize, FLASH_SMEM);

    const int M = Bsz * Tt;  // 4096

    // fused prep: x->fp16 + both weight transposes in one launch
    prep<<<PREP_GRID, 256>>>(x, Wq, Wk, Wv, Wo, Xh, WqkvTh, WoTh);

    // fused QKV projection + rope + rms -> fp16 (Q pre-scaled)
    gemm_qkv<<<dim3(QKVN / 128, M / 128), 128, GEMM_SMEM>>>(Xh, WqkvTh, QKVh, cs, sn);

    // causal GQA flash attention (register-resident P)
    flash_attn_mma<<<dim3(Tt / 128, Hh, Bsz), 128, FLASH_SMEM>>>(QKVh, Yh);

    // output projection
    gemm_wo<<<dim3(Cc / 128, M / 128), 128, GEMM_SMEM>>>(Yh, WoTh, out);
}

// round 15
// speedup vs baseline: 1.1249x; 1.0158x over previous
#include <cuda_runtime.h>
#include <cuda_fp16.h>
#include <math.h>
#include <stdint.h>

#define Bsz 2
#define Tt  2048
#define Cc  1024
#define Hh  16
#define KVh 4
#define HDim 64
#define QKVN 1536   // 1024 Q + 256 K + 256 V
#define QSCALE 0.1803368801111204f   // 0.125 * log2(e)

// -------- scratch (static device globals; no allocation) --------
__device__ __align__(256) __half g_Xh[Bsz * Tt * Cc];
__device__ __align__(256) __half g_QKVh[Bsz * Tt * QKVN];   // fp16, Q pre-scaled
__device__ __align__(256) __half g_Yh[Bsz * Tt * Hh * HDim];
__device__ __align__(256) __half g_WqkvTh[QKVN * Cc];
__device__ __align__(256) __half g_WoTh[Cc * Cc];

__device__ __forceinline__ void mma16816(float* c,
    uint32_t a0, uint32_t a1, uint32_t a2, uint32_t a3,
    uint32_t b0, uint32_t b1) {
    asm volatile(
        "mma.sync.aligned.m16n8k16.row.col.f32.f16.f16.f32 "
        "{%0,%1,%2,%3}, {%4,%5,%6,%7}, {%8,%9}, {%0,%1,%2,%3};"
        : "+f"(c[0]), "+f"(c[1]), "+f"(c[2]), "+f"(c[3])
        : "r"(a0), "r"(a1), "r"(a2), "r"(a3), "r"(b0), "r"(b1));
}

__device__ __forceinline__ void ldmx4(uint32_t* r, uint32_t saddr) {
    asm volatile("ldmatrix.sync.aligned.m8n8.x4.shared.b16 {%0,%1,%2,%3}, [%4];"
        : "=r"(r[0]), "=r"(r[1]), "=r"(r[2]), "=r"(r[3]) : "r"(saddr));
}
__device__ __forceinline__ void ldmx4t(uint32_t* r, uint32_t saddr) {
    asm volatile("ldmatrix.sync.aligned.m8n8.x4.trans.shared.b16 {%0,%1,%2,%3}, [%4];"
        : "=r"(r[0]), "=r"(r[1]), "=r"(r[2]), "=r"(r[3]) : "r"(saddr));
}

__device__ __forceinline__ void cpa16(void* s, const void* g) {
    uint32_t sa = (uint32_t)__cvta_generic_to_shared(s);
    asm volatile("cp.async.ca.shared.global [%0], [%1], 16;" :: "r"(sa), "l"(g));
}
#define CP_COMMIT() asm volatile("cp.async.commit_group;" ::: "memory")
#define CP_WAIT(n)  asm volatile("cp.async.wait_group %0;" :: "n"(n) : "memory")

__device__ __forceinline__ float ex2f(float x) {
    float y;
    asm("ex2.approx.ftz.f32 %0, %1;" : "=f"(y) : "f"(x));
    return y;
}
__device__ __forceinline__ uint32_t packh2(float a, float b) {
    __half2 h = __floats2half2_rn(a, b);
    return *reinterpret_cast<uint32_t*>(&h);
}

// ============================================================
// Fused prep: cvt_x (blocks 0..2047, 32B/thread),
// transpose_qkv (next 1536), transpose Wo (next 1024).
// ============================================================
#define PREP_CVT 2048
#define PREP_QKV 1536
#define PREP_WO  1024
#define PREP_GRID (PREP_CVT + PREP_QKV + PREP_WO)

__global__ __launch_bounds__(256) void prep(
    const float* __restrict__ x,
    const float* __restrict__ Wq, const float* __restrict__ Wk,
    const float* __restrict__ Wv, const float* __restrict__ Wo,
    __half* __restrict__ Xh, __half* __restrict__ WqkvTh,
    __half* __restrict__ WoTh)
{
    int blk = blockIdx.x;
    int tid = threadIdx.x;

    if (blk < PREP_CVT) {
        size_t i = ((size_t)blk * 256 + tid) * 8;
        float4 v0 = *(const float4*)(x + i);
        float4 v1 = *(const float4*)(x + i + 4);
        __half2* o = (__half2*)(Xh + i);
        o[0] = __floats2half2_rn(v0.x, v0.y);
        o[1] = __floats2half2_rn(v0.z, v0.w);
        o[2] = __floats2half2_rn(v1.x, v1.y);
        o[3] = __floats2half2_rn(v1.z, v1.w);
        return;
    }

    __shared__ float tile[32][33];
    int tx = tid & 31, ty = tid >> 5;
    const float* src;
    __half* dst;
    int N, nloc, k0, orow;

    if (blk < PREP_CVT + PREP_QKV) {
        int b = blk - PREP_CVT;
        int nblk = b % 48;
        k0 = (b / 48) * 32;
        if (nblk < 32)      { src = Wq; N = 1024; nloc = nblk * 32; }
        else if (nblk < 40) { src = Wk; N = 256;  nloc = (nblk - 32) * 32; }
        else                { src = Wv; N = 256;  nloc = (nblk - 40) * 32; }
        dst = WqkvTh; orow = nblk * 32;
    } else {
        int b = blk - PREP_CVT - PREP_QKV;
        src = Wo; N = 1024;
        nloc = (b % 32) * 32;
        k0 = (b / 32) * 32;
        dst = WoTh; orow = nloc;
    }

#pragma unroll
    for (int i = 0; i < 32; i += 8)
        tile[ty + i][tx] = src[(size_t)(k0 + ty + i) * N + nloc + tx];
    __syncthreads();
#pragma unroll
    for (int i = 0; i < 32; i += 8)
        dst[(size_t)(orow + ty + i) * Cc + k0 + tx] = __float2half(tile[tx][ty + i]);
}

// ============================================================
// GEMM common: 128 threads, 4 warps of 64x64 (CTA 128x128).
// K-chunk 64, 2-stage cp.async pipeline (16 iterations).
// Stage stride SMH=72 halfs (144B/row, conflict-free ldmatrix).
// ============================================================
#define SMH 72
#define STG_A (128 * SMH)
#define STAGE_H (2 * 128 * SMH)
#define GEMM_SMEM (2 * STAGE_H * 2)   // 73728 bytes; 3 CTAs = 221KB <= 228KB

#define GEMM_MAINLOOP(Aptr, Bptr)                                              \
    float acc[4][8][4];                                                        \
    _Pragma("unroll") for (int mt = 0; mt < 4; mt++)                           \
    _Pragma("unroll") for (int nt = 0; nt < 8; nt++)                           \
    _Pragma("unroll") for (int i = 0; i < 4; i++) acc[mt][nt][i] = 0.f;        \
    auto issue = [&](int st, int kc) {                                         \
        __half* As = sh + st * STAGE_H;                                        \
        __half* Bs = As + STG_A;                                               \
        int r8 = tid >> 3;                                                     \
        int cl = (tid & 7) * 8;                                                \
        _Pragma("unroll") for (int i = 0; i < 8; i++) {                        \
            int row = i * 16 + r8;                                             \
            cpa16(&As[row * SMH + cl], Aptr + (size_t)(bm + row) * 1024 + kc + cl); \
            cpa16(&Bs[row * SMH + cl], Bptr + (size_t)(bn + row) * 1024 + kc + cl); \
        }                                                                      \
        CP_COMMIT();                                                           \
    };                                                                         \
    issue(0, 0);                                                               \
    for (int c = 0; c < 16; c++) {                                             \
        CP_WAIT(0);                                                            \
        __syncthreads();                                                       \
        if (c + 1 < 16) issue((c + 1) & 1, (c + 1) * 64);                      \
        uint32_t As_u = sh_u + (c & 1) * STAGE_H * 2;                          \
        uint32_t Bs_u = As_u + STG_A * 2;                                      \
        _Pragma("unroll") for (int ks = 0; ks < 4; ks++) {                     \
            int k0 = ks * 16;                                                  \
            uint32_t am[4][4], bmx[4][4];                                      \
            _Pragma("unroll") for (int mt = 0; mt < 4; mt++)                   \
                ldmx4(am[mt], As_u + 2 * ((m0 + mt * 16 + aro) * SMH + k0 + aco)); \
            _Pragma("unroll") for (int p = 0; p < 4; p++)                      \
                ldmx4(bmx[p], Bs_u + 2 * ((n0 + p * 16 + bro) * SMH + k0 + bco)); \
            _Pragma("unroll") for (int mt = 0; mt < 4; mt++)                   \
            _Pragma("unroll") for (int p = 0; p < 4; p++) {                    \
                mma16816(acc[mt][2 * p],     am[mt][0], am[mt][1], am[mt][2], am[mt][3], \
                         bmx[p][0], bmx[p][1]);                                \
                mma16816(acc[mt][2 * p + 1], am[mt][0], am[mt][1], am[mt][2], am[mt][3], \
                         bmx[p][2], bmx[p][3]);                                \
            }                                                                  \
        }                                                                      \
    }

#define GEMM_PROLOG                                                            \
    extern __shared__ __half sh[];                                             \
    int tid = threadIdx.x, wid = tid >> 5, lane = tid & 31;                    \
    int gr = lane >> 2, gc = lane & 3;                                         \
    int bm = blockIdx.y * 128, bn = blockIdx.x * 128;                          \
    int m0 = (wid & 1) * 64, n0 = (wid >> 1) * 64;                             \
    const int aro = ((lane & 8) ? 8 : 0) + (lane & 7);                         \
    const int aco = (lane & 16) ? 8 : 0;                                       \
    const int bro = ((lane & 16) ? 8 : 0) + (lane & 7);                        \
    const int bco = (lane & 8) ? 8 : 0;                                        \
    const uint32_t sh_u = (uint32_t)__cvta_generic_to_shared(sh);

// ============================================================
// QKV GEMM + register-local rope/rms epilogue -> fp16 QKVh.
// ============================================================
__global__ __launch_bounds__(128, 3) void gemm_qkv(
    const __half* __restrict__ A, const __half* __restrict__ BT,
    __half* __restrict__ Og,
    const float* __restrict__ cosp, const float* __restrict__ sinp)
{
    GEMM_PROLOG
    GEMM_MAINLOOP(A, BT)

    int ntile = blockIdx.x;
    int hb = bn + n0;

    if (ntile >= 10) {
#pragma unroll
        for (int mt = 0; mt < 4; mt++)
#pragma unroll
            for (int nt = 0; nt < 8; nt++) {
                int row = bm + m0 + mt * 16 + gr;
                int col = hb + nt * 8 + 2 * gc;
                *(__half2*)&Og[(size_t)row * QKVN + col] =
                    __floats2half2_rn(acc[mt][nt][0], acc[mt][nt][1]);
                *(__half2*)&Og[(size_t)(row + 8) * QKVN + col] =
                    __floats2half2_rn(acc[mt][nt][2], acc[mt][nt][3]);
            }
        return;
    }

    float scl = (ntile < 8) ? QSCALE : 1.0f;
#pragma unroll
    for (int mt = 0; mt < 4; mt++) {
#pragma unroll
        for (int j = 0; j < 2; j++) {
            int row = bm + m0 + mt * 16 + gr + j * 8;
            int t = row & (Tt - 1);
            float o1a[4][2], o2a[4][2];
            float ss = 0.f;
#pragma unroll
            for (int nt = 0; nt < 4; nt++) {
                int d = nt * 8 + 2 * gc;
                float2 c2 = *(const float2*)&cosp[t * 32 + d];
                float2 s2 = *(const float2*)&sinp[t * 32 + d];
#pragma unroll
                for (int i = 0; i < 2; i++) {
                    float cv = i ? c2.y : c2.x;
                    float sv = i ? s2.y : s2.x;
                    float x1 = acc[mt][nt][j * 2 + i];
                    float x2 = acc[mt][nt + 4][j * 2 + i];
                    float o1 = x1 * cv + x2 * sv;
                    float o2 = -x1 * sv + x2 * cv;
                    o1a[nt][i] = o1;
                    o2a[nt][i] = o2;
                    ss += o1 * o1 + o2 * o2;
                }
            }
            ss += __shfl_xor_sync(0xffffffffu, ss, 1);
            ss += __shfl_xor_sync(0xffffffffu, ss, 2);
            float inv = rsqrtf(ss * (1.0f / HDim) + 1e-6f) * scl;

            __half* og = Og + (size_t)row * QKVN + hb;
#pragma unroll
            for (int nt = 0; nt < 4; nt++) {
                int d = nt * 8 + 2 * gc;
                *(__half2*)&og[d] =
                    __floats2half2_rn(o1a[nt][0] * inv, o1a[nt][1] * inv);
                *(__half2*)&og[d + 32] =
                    __floats2half2_rn(o2a[nt][0] * inv, o2a[nt][1] * inv);
            }
        }
    }
}

// ============================================================
// Wo GEMM: fp16 in, fp32 out.
// ============================================================
__global__ __launch_bounds__(128, 3) void gemm_wo(
    const __half* __restrict__ A, const __half* __restrict__ BT,
    float* __restrict__ C)
{
    GEMM_PROLOG
    GEMM_MAINLOOP(A, BT)

#pragma unroll
    for (int mt = 0; mt < 4; mt++)
#pragma unroll
        for (int nt = 0; nt < 8; nt++) {
            int row = bm + m0 + mt * 16 + gr;
            int col = bn + n0 + nt * 8 + 2 * gc;
            *(float2*)&C[(size_t)row * Cc + col] =
                make_float2(acc[mt][nt][0], acc[mt][nt][1]);
            *(float2*)&C[(size_t)(row + 8) * Cc + col] =
                make_float2(acc[mt][nt][2], acc[mt][nt][3]);
        }
}

// ============================================================
// fp16 flash attention: 128 threads, 4 warps x 32 q-rows,
// register-resident P, double-buffered KV (unchanged R14).
// ============================================================
#define AST 72
#define QS_OFF 0
#define KS_OFF (128 * AST)
#define VS_OFF (KS_OFF + 2 * 64 * AST)
#define FLASH_SMEM ((128 * AST + 4 * 64 * AST) * 2)   // 55296 bytes

__global__ __launch_bounds__(128) void flash_attn_mma(
    const __half* __restrict__ QKV, __half* __restrict__ Og)
{
    extern __shared__ __half sm[];

    int qb = (gridDim.x - 1) - blockIdx.x;   // LPT: biggest first
    int h = blockIdx.y, b = blockIdx.z;
    int q0 = qb * 128;
    int kvh = h >> 2;
    int tid = threadIdx.x, wid = tid >> 5, lane = tid & 31;
    int gr = lane >> 2, gc = lane & 3;
    int m0 = wid * 32;
    const int aro = ((lane & 8) ? 8 : 0) + (lane & 7);
    const int aco = (lane & 16) ? 8 : 0;
    const int bro = ((lane & 16) ? 8 : 0) + (lane & 7);
    const int bco = (lane & 8) ? 8 : 0;

    const uint32_t sm_u = (uint32_t)__cvta_generic_to_shared(sm);
    const uint32_t Qs_u = sm_u + QS_OFF * 2;

    const __half* Qbase = QKV + (size_t)(b * Tt + q0) * QKVN + h * HDim;
    const __half* KVbase = QKV + (size_t)(b * Tt) * QKVN + 1024 + kvh * HDim;

#pragma unroll
    for (int i = 0; i < 8; i++) {
        int fi = i * 128 + tid;
        int row = fi >> 3, c8 = (fi & 7) * 8;
        cpa16(&sm[QS_OFF + row * AST + c8], Qbase + (size_t)row * QKVN + c8);
    }
    CP_COMMIT();

    auto issueKV = [&](int sbuf, int kt) {
        const __half* Kb = KVbase + (size_t)(kt * 64) * QKVN;
#pragma unroll
        for (int i = 0; i < 4; i++) {
            int fi = i * 128 + tid;
            int row = fi >> 3, c8 = (fi & 7) * 8;
            const __half* g = Kb + (size_t)row * QKVN + c8;
            cpa16(&sm[KS_OFF + sbuf * 64 * AST + row * AST + c8], g);
            cpa16(&sm[VS_OFF + sbuf * 64 * AST + row * AST + c8], g + 256);
        }
        CP_COMMIT();
    };

    issueKV(0, 0);
    CP_WAIT(1);
    __syncthreads();

    uint32_t qf[2][4][4];
#pragma unroll
    for (int mt = 0; mt < 2; mt++)
#pragma unroll
        for (int ks = 0; ks < 4; ks++)
            ldmx4(qf[mt][ks], Qs_u + 2 * ((m0 + mt * 16 + aro) * AST + ks * 16 + aco));

    float o[2][8][4];
#pragma unroll
    for (int mt = 0; mt < 2; mt++)
#pragma unroll
        for (int nt = 0; nt < 8; nt++)
#pragma unroll
            for (int i = 0; i < 4; i++) o[mt][nt][i] = 0.f;
    float mx[2][2], lsum[2][2];
#pragma unroll
    for (int mt = 0; mt < 2; mt++) {
        mx[mt][0] = -1e30f; mx[mt][1] = -1e30f;
        lsum[mt][0] = 0.f;  lsum[mt][1] = 0.f;
    }

    const int nkt = 2 * qb + 2;

    for (int kt = 0; kt < nkt; kt++) {
        int kv0 = kt * 64;
        int buf = kt & 1;
        CP_WAIT(0);
        __syncthreads();
        if (kt + 1 < nkt) issueKV(buf ^ 1, kt + 1);

        uint32_t Ks_u = sm_u + (KS_OFF + buf * 64 * AST) * 2;
        uint32_t Vs_u = sm_u + (VS_OFF + buf * 64 * AST) * 2;

        float s[2][8][4];
#pragma unroll
        for (int mt = 0; mt < 2; mt++)
#pragma unroll
            for (int nt = 0; nt < 8; nt++)
#pragma unroll
                for (int i = 0; i < 4; i++) s[mt][nt][i] = 0.f;

#pragma unroll
        for (int ks = 0; ks < 4; ks++) {
            uint32_t kf[4][4];
#pragma unroll
            for (int p = 0; p < 4; p++)
                ldmx4(kf[p], Ks_u + 2 * ((p * 16 + bro) * AST + ks * 16 + bco));
#pragma unroll
            for (int mt = 0; mt < 2; mt++)
#pragma unroll
                for (int nt = 0; nt < 8; nt++) {
                    int p = nt >> 1, hh = nt & 1;
                    mma16816(s[mt][nt],
                             qf[mt][ks][0], qf[mt][ks][1], qf[mt][ks][2], qf[mt][ks][3],
                             kf[p][2 * hh], kf[p][2 * hh + 1]);
                }
        }

        if (kv0 + 63 > q0) {
#pragma unroll
            for (int mt = 0; mt < 2; mt++) {
                int rl = q0 + m0 + mt * 16 + gr;
                int rh = rl + 8;
#pragma unroll
                for (int nt = 0; nt < 8; nt++) {
                    int c0 = kv0 + nt * 8 + 2 * gc;
                    if (c0 > rl)     s[mt][nt][0] = -1e30f;
                    if (c0 + 1 > rl) s[mt][nt][1] = -1e30f;
                    if (c0 > rh)     s[mt][nt][2] = -1e30f;
                    if (c0 + 1 > rh) s[mt][nt][3] = -1e30f;
                }
            }
        }

        uint32_t pf[2][4][4];
#pragma unroll
        for (int mt = 0; mt < 2; mt++) {
            float tlo = -1e30f, thi = -1e30f;
#pragma unroll
            for (int nt = 0; nt < 8; nt++) {
                tlo = fmaxf(tlo, fmaxf(s[mt][nt][0], s[mt][nt][1]));
                thi = fmaxf(thi, fmaxf(s[mt][nt][2], s[mt][nt][3]));
            }
            tlo = fmaxf(tlo, __shfl_xor_sync(0xffffffffu, tlo, 1));
            tlo = fmaxf(tlo, __shfl_xor_sync(0xffffffffu, tlo, 2));
            thi = fmaxf(thi, __shfl_xor_sync(0xffffffffu, thi, 1));
            thi = fmaxf(thi, __shfl_xor_sync(0xffffffffu, thi, 2));

            float mn_lo = fmaxf(mx[mt][0], tlo);
            float mn_hi = fmaxf(mx[mt][1], thi);
            float cor_lo = ex2f(mx[mt][0] - mn_lo);
            float cor_hi = ex2f(mx[mt][1] - mn_hi);
            mx[mt][0] = mn_lo; mx[mt][1] = mn_hi;
            lsum[mt][0] *= cor_lo; lsum[mt][1] *= cor_hi;
#pragma unroll
            for (int nt = 0; nt < 8; nt++) {
                o[mt][nt][0] *= cor_lo; o[mt][nt][1] *= cor_lo;
                o[mt][nt][2] *= cor_hi; o[mt][nt][3] *= cor_hi;
            }

#pragma unroll
            for (int ks = 0; ks < 4; ks++) {
                float a0 = ex2f(s[mt][2 * ks][0] - mn_lo);
                float a1 = ex2f(s[mt][2 * ks][1] - mn_lo);
                float a2 = ex2f(s[mt][2 * ks][2] - mn_hi);
                float a3 = ex2f(s[mt][2 * ks][3] - mn_hi);
                float b0 = ex2f(s[mt][2 * ks + 1][0] - mn_lo);
                float b1 = ex2f(s[mt][2 * ks + 1][1] - mn_lo);
                float b2 = ex2f(s[mt][2 * ks + 1][2] - mn_hi);
                float b3 = ex2f(s[mt][2 * ks + 1][3] - mn_hi);
                lsum[mt][0] += a0 + a1 + b0 + b1;
                lsum[mt][1] += a2 + a3 + b2 + b3;
                pf[mt][ks][0] = packh2(a0, a1);
                pf[mt][ks][1] = packh2(a2, a3);
                pf[mt][ks][2] = packh2(b0, b1);
                pf[mt][ks][3] = packh2(b2, b3);
            }
        }

#pragma unroll
        for (int ks = 0; ks < 4; ks++) {
            uint32_t vf[4][4];
#pragma unroll
            for (int p = 0; p < 4; p++)
                ldmx4t(vf[p], Vs_u + 2 * ((ks * 16 + aro) * AST + p * 16 + aco));
#pragma unroll
            for (int mt = 0; mt < 2; mt++)
#pragma unroll
                for (int nt = 0; nt < 8; nt++) {
                    int p = nt >> 1, hh = nt & 1;
                    mma16816(o[mt][nt],
                             pf[mt][ks][0], pf[mt][ks][1], pf[mt][ks][2], pf[mt][ks][3],
                             vf[p][2 * hh], vf[p][2 * hh + 1]);
                }
        }
    }

    __half* Obase = Og + ((size_t)(b * Tt) * Hh + h) * HDim;
#pragma unroll
    for (int mt = 0; mt < 2; mt++) {
        float llo = lsum[mt][0], lhi = lsum[mt][1];
        llo += __shfl_xor_sync(0xffffffffu, llo, 1);
        llo += __shfl_xor_sync(0xffffffffu, llo, 2);
        lhi += __shfl_xor_sync(0xffffffffu, lhi, 1);
        lhi += __shfl_xor_sync(0xffffffffu, lhi, 2);
        float inv_lo = 1.f / llo;
        float inv_hi = 1.f / lhi;

        int row_lo = q0 + m0 + mt * 16 + gr;
        int row_hi = row_lo + 8;
#pragma unroll
        for (int nt = 0; nt < 8; nt++) {
            int col = nt * 8 + 2 * gc;
            *(__half2*)&Obase[(size_t)row_lo * (Hh * HDim) + col] =
                __floats2half2_rn(o[mt][nt][0] * inv_lo, o[mt][nt][1] * inv_lo);
            *(__half2*)&Obase[(size_t)row_hi * (Hh * HDim) + col] =
                __floats2half2_rn(o[mt][nt][2] * inv_hi, o[mt][nt][3] * inv_hi);
        }
    }
}

// ============================================================
// launch
// ============================================================
extern "C" void kernel_launch(void* const* d_in, const int* in_sizes, int n_in,
                              void* d_out, int out_size)
{
    const float* x  = (const float*)d_in[0];
    const float* cs = (const float*)d_in[1];
    const float* sn = (const float*)d_in[2];
    const float* Wq = (const float*)d_in[3];
    const float* Wk = (const float*)d_in[4];
    const float* Wv = (const float*)d_in[5];
    const float* Wo = (const float*)d_in[6];
    float* out = (float*)d_out;

    __half *Xh, *QKVh, *Yh, *WqkvTh, *WoTh;
    cudaGetSymbolAddress((void**)&Xh, g_Xh);
    cudaGetSymbolAddress((void**)&QKVh, g_QKVh);
    cudaGetSymbolAddress((void**)&Yh, g_Yh);
    cudaGetSymbolAddress((void**)&WqkvTh, g_WqkvTh);
    cudaGetSymbolAddress((void**)&WoTh, g_WoTh);

    cudaFuncSetAttribute(gemm_qkv,
                         cudaFuncAttributeMaxDynamicSharedMemorySize, GEMM_SMEM);
    cudaFuncSetAttribute(gemm_wo,
                         cudaFuncAttributeMaxDynamicSharedMemorySize, GEMM_SMEM);
    cudaFuncSetAttribute(flash_attn_mma,
                         cudaFuncAttributeMaxDynamicSharedMemorySize, FLASH_SMEM);

    const int M = Bsz * Tt;  // 4096

    // fused prep: x->fp16 + both weight transposes in one launch
    prep<<<PREP_GRID, 256>>>(x, Wq, Wk, Wv, Wo, Xh, WqkvTh, WoTh);

    // fused QKV projection + rope + rms -> fp16 (Q pre-scaled)
    gemm_qkv<<<dim3(QKVN / 128, M / 128), 128, GEMM_SMEM>>>(Xh, WqkvTh, QKVh, cs, sn);

    // causal GQA flash attention (register-resident P)
    flash_attn_mma<<<dim3(Tt / 128, Hh, Bsz), 128, FLASH_SMEM>>>(QKVh, Yh);

    // output projection
    gemm_wo<<<dim3(Cc / 128, M / 128), 128, GEMM_SMEM>>>(Yh, WoTh, out);
}

// round 16
// speedup vs baseline: 1.1365x; 1.0102x over previous
#include <cuda_runtime.h>
#include <cuda_fp16.h>
#include <math.h>
#include <stdint.h>

#define Bsz 2
#define Tt  2048
#define Cc  1024
#define Hh  16
#define KVh 4
#define HDim 64
#define QKVN 1536   // 1024 Q + 256 K + 256 V
#define QSCALE 0.1803368801111204f   // 0.125 * log2(e)

// -------- scratch (static device globals; no allocation) --------
__device__ __align__(256) __half g_Xh[Bsz * Tt * Cc];
__device__ __align__(256) __half g_QKVh[Bsz * Tt * QKVN];   // fp16, Q pre-scaled
__device__ __align__(256) __half g_Yh[Bsz * Tt * Hh * HDim];
__device__ __align__(256) __half g_WqkvTh[QKVN * Cc];
__device__ __align__(256) __half g_WoTh[Cc * Cc];

__device__ __forceinline__ void mma16816(float* c,
    uint32_t a0, uint32_t a1, uint32_t a2, uint32_t a3,
    uint32_t b0, uint32_t b1) {
    asm volatile(
        "mma.sync.aligned.m16n8k16.row.col.f32.f16.f16.f32 "
        "{%0,%1,%2,%3}, {%4,%5,%6,%7}, {%8,%9}, {%0,%1,%2,%3};"
        : "+f"(c[0]), "+f"(c[1]), "+f"(c[2]), "+f"(c[3])
        : "r"(a0), "r"(a1), "r"(a2), "r"(a3), "r"(b0), "r"(b1));
}

__device__ __forceinline__ void ldmx4(uint32_t* r, uint32_t saddr) {
    asm volatile("ldmatrix.sync.aligned.m8n8.x4.shared.b16 {%0,%1,%2,%3}, [%4];"
        : "=r"(r[0]), "=r"(r[1]), "=r"(r[2]), "=r"(r[3]) : "r"(saddr));
}
__device__ __forceinline__ void ldmx4t(uint32_t* r, uint32_t saddr) {
    asm volatile("ldmatrix.sync.aligned.m8n8.x4.trans.shared.b16 {%0,%1,%2,%3}, [%4];"
        : "=r"(r[0]), "=r"(r[1]), "=r"(r[2]), "=r"(r[3]) : "r"(saddr));
}

__device__ __forceinline__ void cpa16(void* s, const void* g) {
    uint32_t sa = (uint32_t)__cvta_generic_to_shared(s);
    asm volatile("cp.async.ca.shared.global [%0], [%1], 16;" :: "r"(sa), "l"(g));
}
#define CP_COMMIT() asm volatile("cp.async.commit_group;" ::: "memory")
#define CP_WAIT(n)  asm volatile("cp.async.wait_group %0;" :: "n"(n) : "memory")

__device__ __forceinline__ float ex2f(float x) {
    float y;
    asm("ex2.approx.ftz.f32 %0, %1;" : "=f"(y) : "f"(x));
    return y;
}
__device__ __forceinline__ uint32_t packh2(float a, float b) {
    __half2 h = __floats2half2_rn(a, b);
    return *reinterpret_cast<uint32_t*>(&h);
}

// ============================================================
// Fused prep: cvt_x (blocks 0..2047, 32B/thread),
// transpose_qkv (next 1536), transpose Wo (next 1024).
// ============================================================
#define PREP_CVT 2048
#define PREP_QKV 1536
#define PREP_WO  1024
#define PREP_GRID (PREP_CVT + PREP_QKV + PREP_WO)

__global__ __launch_bounds__(256) void prep(
    const float* __restrict__ x,
    const float* __restrict__ Wq, const float* __restrict__ Wk,
    const float* __restrict__ Wv, const float* __restrict__ Wo,
    __half* __restrict__ Xh, __half* __restrict__ WqkvTh,
    __half* __restrict__ WoTh)
{
    int blk = blockIdx.x;
    int tid = threadIdx.x;

    if (blk < PREP_CVT) {
        size_t i = ((size_t)blk * 256 + tid) * 8;
        float4 v0 = *(const float4*)(x + i);
        float4 v1 = *(const float4*)(x + i + 4);
        __half2* o = (__half2*)(Xh + i);
        o[0] = __floats2half2_rn(v0.x, v0.y);
        o[1] = __floats2half2_rn(v0.z, v0.w);
        o[2] = __floats2half2_rn(v1.x, v1.y);
        o[3] = __floats2half2_rn(v1.z, v1.w);
        return;
    }

    __shared__ float tile[32][33];
    int tx = tid & 31, ty = tid >> 5;
    const float* src;
    __half* dst;
    int N, nloc, k0, orow;

    if (blk < PREP_CVT + PREP_QKV) {
        int b = blk - PREP_CVT;
        int nblk = b % 48;
        k0 = (b / 48) * 32;
        if (nblk < 32)      { src = Wq; N = 1024; nloc = nblk * 32; }
        else if (nblk < 40) { src = Wk; N = 256;  nloc = (nblk - 32) * 32; }
        else                { src = Wv; N = 256;  nloc = (nblk - 40) * 32; }
        dst = WqkvTh; orow = nblk * 32;
    } else {
        int b = blk - PREP_CVT - PREP_QKV;
        src = Wo; N = 1024;
        nloc = (b % 32) * 32;
        k0 = (b / 32) * 32;
        dst = WoTh; orow = nloc;
    }

#pragma unroll
    for (int i = 0; i < 32; i += 8)
        tile[ty + i][tx] = src[(size_t)(k0 + ty + i) * N + nloc + tx];
    __syncthreads();
#pragma unroll
    for (int i = 0; i < 32; i += 8)
        dst[(size_t)(orow + ty + i) * Cc + k0 + tx] = __float2half(tile[tx][ty + i]);
}

// ============================================================
// GEMM common: 128 threads, 4 warps of 64x64 (CTA 128x128).
// K-chunk 64, 2-stage cp.async, DOUBLE-BUFFERED FRAGMENTS:
// ldmatrix for ks+1 issued before MMAs of ks (hides LDS latency).
// ============================================================
#define SMH 72
#define STG_A (128 * SMH)
#define STAGE_H (2 * 128 * SMH)
#define GEMM_SMEM (2 * STAGE_H * 2)   // 73728 bytes

#define GEMM_MAINLOOP(Aptr, Bptr)                                              \
    float acc[4][8][4];                                                        \
    _Pragma("unroll") for (int mt = 0; mt < 4; mt++)                           \
    _Pragma("unroll") for (int nt = 0; nt < 8; nt++)                           \
    _Pragma("unroll") for (int i = 0; i < 4; i++) acc[mt][nt][i] = 0.f;        \
    auto issue = [&](int st, int kc) {                                         \
        __half* As = sh + st * STAGE_H;                                        \
        __half* Bs = As + STG_A;                                               \
        int r8 = tid >> 3;                                                     \
        int cl = (tid & 7) * 8;                                                \
        _Pragma("unroll") for (int i = 0; i < 8; i++) {                        \
            int row = i * 16 + r8;                                             \
            cpa16(&As[row * SMH + cl], Aptr + (size_t)(bm + row) * 1024 + kc + cl); \
            cpa16(&Bs[row * SMH + cl], Bptr + (size_t)(bn + row) * 1024 + kc + cl); \
        }                                                                      \
        CP_COMMIT();                                                           \
    };                                                                         \
    uint32_t am[2][4][4], bmx[2][4][4];                                        \
    auto ldfr = [&](uint32_t base_u, int fb, int k0) {                         \
        uint32_t As_u = base_u;                                                \
        uint32_t Bs_u = base_u + STG_A * 2;                                    \
        _Pragma("unroll") for (int mt = 0; mt < 4; mt++)                       \
            ldmx4(am[fb][mt], As_u + 2 * ((m0 + mt * 16 + aro) * SMH + k0 + aco)); \
        _Pragma("unroll") for (int p = 0; p < 4; p++)                          \
            ldmx4(bmx[fb][p], Bs_u + 2 * ((n0 + p * 16 + bro) * SMH + k0 + bco)); \
    };                                                                         \
    issue(0, 0);                                                               \
    for (int c = 0; c < 16; c++) {                                             \
        CP_WAIT(0);                                                            \
        __syncthreads();                                                       \
        uint32_t base_u = sh_u + (c & 1) * STAGE_H * 2;                        \
        ldfr(base_u, 0, 0);                                                    \
        if (c + 1 < 16) issue((c + 1) & 1, (c + 1) * 64);                      \
        _Pragma("unroll") for (int ks = 0; ks < 4; ks++) {                     \
            if (ks < 3) ldfr(base_u, (ks + 1) & 1, (ks + 1) * 16);             \
            int rb = ks & 1;                                                   \
            _Pragma("unroll") for (int mt = 0; mt < 4; mt++)                   \
            _Pragma("unroll") for (int p = 0; p < 4; p++) {                    \
                mma16816(acc[mt][2 * p],                                       \
                         am[rb][mt][0], am[rb][mt][1], am[rb][mt][2], am[rb][mt][3], \
                         bmx[rb][p][0], bmx[rb][p][1]);                        \
                mma16816(acc[mt][2 * p + 1],                                   \
                         am[rb][mt][0], am[rb][mt][1], am[rb][mt][2], am[rb][mt][3], \
                         bmx[rb][p][2], bmx[rb][p][3]);                        \
            }                                                                  \
        }                                                                      \
    }

#define GEMM_PROLOG                                                            \
    extern __shared__ __half sh[];                                             \
    int tid = threadIdx.x, wid = tid >> 5, lane = tid & 31;                    \
    int gr = lane >> 2, gc = lane & 3;                                         \
    int bm = blockIdx.y * 128, bn = blockIdx.x * 128;                          \
    int m0 = (wid & 1) * 64, n0 = (wid >> 1) * 64;                             \
    const int aro = ((lane & 8) ? 8 : 0) + (lane & 7);                         \
    const int aco = (lane & 16) ? 8 : 0;                                       \
    const int bro = ((lane & 16) ? 8 : 0) + (lane & 7);                        \
    const int bco = (lane & 8) ? 8 : 0;                                        \
    const uint32_t sh_u = (uint32_t)__cvta_generic_to_shared(sh);

// ============================================================
// QKV GEMM + register-local rope/rms epilogue -> fp16 QKVh.
// ============================================================
__global__ __launch_bounds__(128, 2) void gemm_qkv(
    const __half* __restrict__ A, const __half* __restrict__ BT,
    __half* __restrict__ Og,
    const float* __restrict__ cosp, const float* __restrict__ sinp)
{
    GEMM_PROLOG
    GEMM_MAINLOOP(A, BT)

    int ntile = blockIdx.x;
    int hb = bn + n0;

    if (ntile >= 10) {
#pragma unroll
        for (int mt = 0; mt < 4; mt++)
#pragma unroll
            for (int nt = 0; nt < 8; nt++) {
                int row = bm + m0 + mt * 16 + gr;
                int col = hb + nt * 8 + 2 * gc;
                *(__half2*)&Og[(size_t)row * QKVN + col] =
                    __floats2half2_rn(acc[mt][nt][0], acc[mt][nt][1]);
                *(__half2*)&Og[(size_t)(row + 8) * QKVN + col] =
                    __floats2half2_rn(acc[mt][nt][2], acc[mt][nt][3]);
            }
        return;
    }

    float scl = (ntile < 8) ? QSCALE : 1.0f;
#pragma unroll
    for (int mt = 0; mt < 4; mt++) {
#pragma unroll
        for (int j = 0; j < 2; j++) {
            int row = bm + m0 + mt * 16 + gr + j * 8;
            int t = row & (Tt - 1);
            float o1a[4][2], o2a[4][2];
            float ss = 0.f;
#pragma unroll
            for (int nt = 0; nt < 4; nt++) {
                int d = nt * 8 + 2 * gc;
                float2 c2 = *(const float2*)&cosp[t * 32 + d];
                float2 s2 = *(const float2*)&sinp[t * 32 + d];
#pragma unroll
                for (int i = 0; i < 2; i++) {
                    float cv = i ? c2.y : c2.x;
                    float sv = i ? s2.y : s2.x;
                    float x1 = acc[mt][nt][j * 2 + i];
                    float x2 = acc[mt][nt + 4][j * 2 + i];
                    float o1 = x1 * cv + x2 * sv;
                    float o2 = -x1 * sv + x2 * cv;
                    o1a[nt][i] = o1;
                    o2a[nt][i] = o2;
                    ss += o1 * o1 + o2 * o2;
                }
            }
            ss += __shfl_xor_sync(0xffffffffu, ss, 1);
            ss += __shfl_xor_sync(0xffffffffu, ss, 2);
            float inv = rsqrtf(ss * (1.0f / HDim) + 1e-6f) * scl;

            __half* og = Og + (size_t)row * QKVN + hb;
#pragma unroll
            for (int nt = 0; nt < 4; nt++) {
                int d = nt * 8 + 2 * gc;
                *(__half2*)&og[d] =
                    __floats2half2_rn(o1a[nt][0] * inv, o1a[nt][1] * inv);
                *(__half2*)&og[d + 32] =
                    __floats2half2_rn(o2a[nt][0] * inv, o2a[nt][1] * inv);
            }
        }
    }
}

// ============================================================
// Wo GEMM: fp16 in, fp32 out.
// ============================================================
__global__ __launch_bounds__(128, 2) void gemm_wo(
    const __half* __restrict__ A, const __half* __restrict__ BT,
    float* __restrict__ C)
{
    GEMM_PROLOG
    GEMM_MAINLOOP(A, BT)

#pragma unroll
    for (int mt = 0; mt < 4; mt++)
#pragma unroll
        for (int nt = 0; nt < 8; nt++) {
            int row = bm + m0 + mt * 16 + gr;
            int col = bn + n0 + nt * 8 + 2 * gc;
            *(float2*)&C[(size_t)row * Cc + col] =
                make_float2(acc[mt][nt][0], acc[mt][nt][1]);
            *(float2*)&C[(size_t)(row + 8) * Cc + col] =
                make_float2(acc[mt][nt][2], acc[mt][nt][3]);
        }
}

// ============================================================
// fp16 flash attention: 128 threads, 4 warps x 32 q-rows,
// register-resident P, double-buffered KV (unchanged).
// ============================================================
#define AST 72
#define QS_OFF 0
#define KS_OFF (128 * AST)
#define VS_OFF (KS_OFF + 2 * 64 * AST)
#define FLASH_SMEM ((128 * AST + 4 * 64 * AST) * 2)   // 55296 bytes

__global__ __launch_bounds__(128) void flash_attn_mma(
    const __half* __restrict__ QKV, __half* __restrict__ Og)
{
    extern __shared__ __half sm[];

    int qb = (gridDim.x - 1) - blockIdx.x;   // LPT: biggest first
    int h = blockIdx.y, b = blockIdx.z;
    int q0 = qb * 128;
    int kvh = h >> 2;
    int tid = threadIdx.x, wid = tid >> 5, lane = tid & 31;
    int gr = lane >> 2, gc = lane & 3;
    int m0 = wid * 32;
    const int aro = ((lane & 8) ? 8 : 0) + (lane & 7);
    const int aco = (lane & 16) ? 8 : 0;
    const int bro = ((lane & 16) ? 8 : 0) + (lane & 7);
    const int bco = (lane & 8) ? 8 : 0;

    const uint32_t sm_u = (uint32_t)__cvta_generic_to_shared(sm);
    const uint32_t Qs_u = sm_u + QS_OFF * 2;

    const __half* Qbase = QKV + (size_t)(b * Tt + q0) * QKVN + h * HDim;
    const __half* KVbase = QKV + (size_t)(b * Tt) * QKVN + 1024 + kvh * HDim;

#pragma unroll
    for (int i = 0; i < 8; i++) {
        int fi = i * 128 + tid;
        int row = fi >> 3, c8 = (fi & 7) * 8;
        cpa16(&sm[QS_OFF + row * AST + c8], Qbase + (size_t)row * QKVN + c8);
    }
    CP_COMMIT();

    auto issueKV = [&](int sbuf, int kt) {
        const __half* Kb = KVbase + (size_t)(kt * 64) * QKVN;
#pragma unroll
        for (int i = 0; i < 4; i++) {
            int fi = i * 128 + tid;
            int row = fi >> 3, c8 = (fi & 7) * 8;
            const __half* g = Kb + (size_t)row * QKVN + c8;
            cpa16(&sm[KS_OFF + sbuf * 64 * AST + row * AST + c8], g);
            cpa16(&sm[VS_OFF + sbuf * 64 * AST + row * AST + c8], g + 256);
        }
        CP_COMMIT();
    };

    issueKV(0, 0);
    CP_WAIT(1);
    __syncthreads();

    uint32_t qf[2][4][4];
#pragma unroll
    for (int mt = 0; mt < 2; mt++)
#pragma unroll
        for (int ks = 0; ks < 4; ks++)
            ldmx4(qf[mt][ks], Qs_u + 2 * ((m0 + mt * 16 + aro) * AST + ks * 16 + aco));

    float o[2][8][4];
#pragma unroll
    for (int mt = 0; mt < 2; mt++)
#pragma unroll
        for (int nt = 0; nt < 8; nt++)
#pragma unroll
            for (int i = 0; i < 4; i++) o[mt][nt][i] = 0.f;
    float mx[2][2], lsum[2][2];
#pragma unroll
    for (int mt = 0; mt < 2; mt++) {
        mx[mt][0] = -1e30f; mx[mt][1] = -1e30f;
        lsum[mt][0] = 0.f;  lsum[mt][1] = 0.f;
    }

    const int nkt = 2 * qb + 2;

    for (int kt = 0; kt < nkt; kt++) {
        int kv0 = kt * 64;
        int buf = kt & 1;
        CP_WAIT(0);
        __syncthreads();
        if (kt + 1 < nkt) issueKV(buf ^ 1, kt + 1);

        uint32_t Ks_u = sm_u + (KS_OFF + buf * 64 * AST) * 2;
        uint32_t Vs_u = sm_u + (VS_OFF + buf * 64 * AST) * 2;

        float s[2][8][4];
#pragma unroll
        for (int mt = 0; mt < 2; mt++)
#pragma unroll
            for (int nt = 0; nt < 8; nt++)
#pragma unroll
                for (int i = 0; i < 4; i++) s[mt][nt][i] = 0.f;

#pragma unroll
        for (int ks = 0; ks < 4; ks++) {
            uint32_t kf[4][4];
#pragma unroll
            for (int p = 0; p < 4; p++)
                ldmx4(kf[p], Ks_u + 2 * ((p * 16 + bro) * AST + ks * 16 + bco));
#pragma unroll
            for (int mt = 0; mt < 2; mt++)
#pragma unroll
                for (int nt = 0; nt < 8; nt++) {
                    int p = nt >> 1, hh = nt & 1;
                    mma16816(s[mt][nt],
                             qf[mt][ks][0], qf[mt][ks][1], qf[mt][ks][2], qf[mt][ks][3],
                             kf[p][2 * hh], kf[p][2 * hh + 1]);
                }
        }

        if (kv0 + 63 > q0) {
#pragma unroll
            for (int mt = 0; mt < 2; mt++) {
                int rl = q0 + m0 + mt * 16 + gr;
                int rh = rl + 8;
#pragma unroll
                for (int nt = 0; nt < 8; nt++) {
                    int c0 = kv0 + nt * 8 + 2 * gc;
                    if (c0 > rl)     s[mt][nt][0] = -1e30f;
                    if (c0 + 1 > rl) s[mt][nt][1] = -1e30f;
                    if (c0 > rh)     s[mt][nt][2] = -1e30f;
                    if (c0 + 1 > rh) s[mt][nt][3] = -1e30f;
                }
            }
        }

        uint32_t pf[2][4][4];
#pragma unroll
        for (int mt = 0; mt < 2; mt++) {
            float tlo = -1e30f, thi = -1e30f;
#pragma unroll
            for (int nt = 0; nt < 8; nt++) {
                tlo = fmaxf(tlo, fmaxf(s[mt][nt][0], s[mt][nt][1]));
                thi = fmaxf(thi, fmaxf(s[mt][nt][2], s[mt][nt][3]));
            }
            tlo = fmaxf(tlo, __shfl_xor_sync(0xffffffffu, tlo, 1));
            tlo = fmaxf(tlo, __shfl_xor_sync(0xffffffffu, tlo, 2));
            thi = fmaxf(thi, __shfl_xor_sync(0xffffffffu, thi, 1));
            thi = fmaxf(thi, __shfl_xor_sync(0xffffffffu, thi, 2));

            float mn_lo = fmaxf(mx[mt][0], tlo);
            float mn_hi = fmaxf(mx[mt][1], thi);
            float cor_lo = ex2f(mx[mt][0] - mn_lo);
            float cor_hi = ex2f(mx[mt][1] - mn_hi);
            mx[mt][0] = mn_lo; mx[mt][1] = mn_hi;
            lsum[mt][0] *= cor_lo; lsum[mt][1] *= cor_hi;
#pragma unroll
            for (int nt = 0; nt < 8; nt++) {
                o[mt][nt][0] *= cor_lo; o[mt][nt][1] *= cor_lo;
                o[mt][nt][2] *= cor_hi; o[mt][nt][3] *= cor_hi;
            }

#pragma unroll
            for (int ks = 0; ks < 4; ks++) {
                float a0 = ex2f(s[mt][2 * ks][0] - mn_lo);
                float a1 = ex2f(s[mt][2 * ks][1] - mn_lo);
                float a2 = ex2f(s[mt][2 * ks][2] - mn_hi);
                float a3 = ex2f(s[mt][2 * ks][3] - mn_hi);
                float b0 = ex2f(s[mt][2 * ks + 1][0] - mn_lo);
                float b1 = ex2f(s[mt][2 * ks + 1][1] - mn_lo);
                float b2 = ex2f(s[mt][2 * ks + 1][2] - mn_hi);
                float b3 = ex2f(s[mt][2 * ks + 1][3] - mn_hi);
                lsum[mt][0] += a0 + a1 + b0 + b1;
                lsum[mt][1] += a2 + a3 + b2 + b3;
                pf[mt][ks][0] = packh2(a0, a1);
                pf[mt][ks][1] = packh2(a2, a3);
                pf[mt][ks][2] = packh2(b0, b1);
                pf[mt][ks][3] = packh2(b2, b3);
            }
        }

#pragma unroll
        for (int ks = 0; ks < 4; ks++) {
            uint32_t vf[4][4];
#pragma unroll
            for (int p = 0; p < 4; p++)
                ldmx4t(vf[p], Vs_u + 2 * ((ks * 16 + aro) * AST + p * 16 + aco));
#pragma unroll
            for (int mt = 0; mt < 2; mt++)
#pragma unroll
                for (int nt = 0; nt < 8; nt++) {
                    int p = nt >> 1, hh = nt & 1;
                    mma16816(o[mt][nt],
                             pf[mt][ks][0], pf[mt][ks][1], pf[mt][ks][2], pf[mt][ks][3],
                             vf[p][2 * hh], vf[p][2 * hh + 1]);
                }
        }
    }

    __half* Obase = Og + ((size_t)(b * Tt) * Hh + h) * HDim;
#pragma unroll
    for (int mt = 0; mt < 2; mt++) {
        float llo = lsum[mt][0], lhi = lsum[mt][1];
        llo += __shfl_xor_sync(0xffffffffu, llo, 1);
        llo += __shfl_xor_sync(0xffffffffu, llo, 2);
        lhi += __shfl_xor_sync(0xffffffffu, lhi, 1);
        lhi += __shfl_xor_sync(0xffffffffu, lhi, 2);
        float inv_lo = 1.f / llo;
        float inv_hi = 1.f / lhi;

        int row_lo = q0 + m0 + mt * 16 + gr;
        int row_hi = row_lo + 8;
#pragma unroll
        for (int nt = 0; nt < 8; nt++) {
            int col = nt * 8 + 2 * gc;
            *(__half2*)&Obase[(size_t)row_lo * (Hh * HDim) + col] =
                __floats2half2_rn(o[mt][nt][0] * inv_lo, o[mt][nt][1] * inv_lo);
            *(__half2*)&Obase[(size_t)row_hi * (Hh * HDim) + col] =
                __floats2half2_rn(o[mt][nt][2] * inv_hi, o[mt][nt][3] * inv_hi);
        }
    }
}

// ============================================================
// launch
// ============================================================
extern "C" void kernel_launch(void* const* d_in, const int* in_sizes, int n_in,
                              void* d_out, int out_size)
{
    const float* x  = (const float*)d_in[0];
    const float* cs = (const float*)d_in[1];
    const float* sn = (const float*)d_in[2];
    const float* Wq = (const float*)d_in[3];
    const float* Wk = (const float*)d_in[4];
    const float* Wv = (const float*)d_in[5];
    const float* Wo = (const float*)d_in[6];
    float* out = (float*)d_out;

    __half *Xh, *QKVh, *Yh, *WqkvTh, *WoTh;
    cudaGetSymbolAddress((void**)&Xh, g_Xh);
    cudaGetSymbolAddress((void**)&QKVh, g_QKVh);
    cudaGetSymbolAddress((void**)&Yh, g_Yh);
    cudaGetSymbolAddress((void**)&WqkvTh, g_WqkvTh);
    cudaGetSymbolAddress((void**)&WoTh, g_WoTh);

    cudaFuncSetAttribute(gemm_qkv,
                         cudaFuncAttributeMaxDynamicSharedMemorySize, GEMM_SMEM);
    cudaFuncSetAttribute(gemm_wo,
                         cudaFuncAttributeMaxDynamicSharedMemorySize, GEMM_SMEM);
    cudaFuncSetAttribute(flash_attn_mma,
                         cudaFuncAttributeMaxDynamicSharedMemorySize, FLASH_SMEM);

    const int M = Bsz * Tt;  // 4096

    // fused prep: x->fp16 + both weight transposes in one launch
    prep<<<PREP_GRID, 256>>>(x, Wq, Wk, Wv, Wo, Xh, WqkvTh, WoTh);

    // fused QKV projection + rope + rms -> fp16 (Q pre-scaled)
    gemm_qkv<<<dim3(QKVN / 128, M / 128), 128, GEMM_SMEM>>>(Xh, WqkvTh, QKVh, cs, sn);

    // causal GQA flash attention (register-resident P)
    flash_attn_mma<<<dim3(Tt / 128, Hh, Bsz), 128, FLASH_SMEM>>>(QKVh, Yh);

    // output projection
    gemm_wo<<<dim3(Cc / 128, M / 128), 128, GEMM_SMEM>>>(Yh, WoTh, out);
}

// round 17
// speedup vs baseline: 1.1423x; 1.0051x over previous
#include <cuda_runtime.h>
#include <cuda_fp16.h>
#include <math.h>
#include <stdint.h>

#define Bsz 2
#define Tt  2048
#define Cc  1024
#define Hh  16
#define KVh 4
#define HDim 64
#define QKVN 1536   // 1024 Q + 256 K + 256 V
#define QSCALE 0.1803368801111204f   // 0.125 * log2(e)

// -------- scratch (static device globals; no allocation) --------
__device__ __align__(256) __half g_Xh[Bsz * Tt * Cc];
__device__ __align__(256) __half g_QKVh[Bsz * Tt * QKVN];   // fp16, Q pre-scaled
__device__ __align__(256) __half g_Yh[Bsz * Tt * Hh * HDim];
__device__ __align__(256) __half g_WqkvTh[QKVN * Cc];
__device__ __align__(256) __half g_WoTh[Cc * Cc];

__device__ __forceinline__ void mma16816(float* c,
    uint32_t a0, uint32_t a1, uint32_t a2, uint32_t a3,
    uint32_t b0, uint32_t b1) {
    asm volatile(
        "mma.sync.aligned.m16n8k16.row.col.f32.f16.f16.f32 "
        "{%0,%1,%2,%3}, {%4,%5,%6,%7}, {%8,%9}, {%0,%1,%2,%3};"
        : "+f"(c[0]), "+f"(c[1]), "+f"(c[2]), "+f"(c[3])
        : "r"(a0), "r"(a1), "r"(a2), "r"(a3), "r"(b0), "r"(b1));
}

__device__ __forceinline__ void ldmx4(uint32_t* r, uint32_t saddr) {
    asm volatile("ldmatrix.sync.aligned.m8n8.x4.shared.b16 {%0,%1,%2,%3}, [%4];"
        : "=r"(r[0]), "=r"(r[1]), "=r"(r[2]), "=r"(r[3]) : "r"(saddr));
}
__device__ __forceinline__ void ldmx4t(uint32_t* r, uint32_t saddr) {
    asm volatile("ldmatrix.sync.aligned.m8n8.x4.trans.shared.b16 {%0,%1,%2,%3}, [%4];"
        : "=r"(r[0]), "=r"(r[1]), "=r"(r[2]), "=r"(r[3]) : "r"(saddr));
}

__device__ __forceinline__ void cpa16(void* s, const void* g) {
    uint32_t sa = (uint32_t)__cvta_generic_to_shared(s);
    asm volatile("cp.async.ca.shared.global [%0], [%1], 16;" :: "r"(sa), "l"(g));
}
#define CP_COMMIT() asm volatile("cp.async.commit_group;" ::: "memory")
#define CP_WAIT(n)  asm volatile("cp.async.wait_group %0;" :: "n"(n) : "memory")

__device__ __forceinline__ float ex2f(float x) {
    float y;
    asm("ex2.approx.ftz.f32 %0, %1;" : "=f"(y) : "f"(x));
    return y;
}
__device__ __forceinline__ uint32_t packh2(float a, float b) {
    __half2 h = __floats2half2_rn(a, b);
    return *reinterpret_cast<uint32_t*>(&h);
}

// ============================================================
// Fused prep
// ============================================================
#define PREP_CVT 2048
#define PREP_QKV 1536
#define PREP_WO  1024
#define PREP_GRID (PREP_CVT + PREP_QKV + PREP_WO)

__global__ __launch_bounds__(256) void prep(
    const float* __restrict__ x,
    const float* __restrict__ Wq, const float* __restrict__ Wk,
    const float* __restrict__ Wv, const float* __restrict__ Wo,
    __half* __restrict__ Xh, __half* __restrict__ WqkvTh,
    __half* __restrict__ WoTh)
{
    int blk = blockIdx.x;
    int tid = threadIdx.x;

    if (blk < PREP_CVT) {
        size_t i = ((size_t)blk * 256 + tid) * 8;
        float4 v0 = *(const float4*)(x + i);
        float4 v1 = *(const float4*)(x + i + 4);
        __half2* o = (__half2*)(Xh + i);
        o[0] = __floats2half2_rn(v0.x, v0.y);
        o[1] = __floats2half2_rn(v0.z, v0.w);
        o[2] = __floats2half2_rn(v1.x, v1.y);
        o[3] = __floats2half2_rn(v1.z, v1.w);
        return;
    }

    __shared__ float tile[32][33];
    int tx = tid & 31, ty = tid >> 5;
    const float* src;
    __half* dst;
    int N, nloc, k0, orow;

    if (blk < PREP_CVT + PREP_QKV) {
        int b = blk - PREP_CVT;
        int nblk = b % 48;
        k0 = (b / 48) * 32;
        if (nblk < 32)      { src = Wq; N = 1024; nloc = nblk * 32; }
        else if (nblk < 40) { src = Wk; N = 256;  nloc = (nblk - 32) * 32; }
        else                { src = Wv; N = 256;  nloc = (nblk - 40) * 32; }
        dst = WqkvTh; orow = nblk * 32;
    } else {
        int b = blk - PREP_CVT - PREP_QKV;
        src = Wo; N = 1024;
        nloc = (b % 32) * 32;
        k0 = (b / 32) * 32;
        dst = WoTh; orow = nloc;
    }

#pragma unroll
    for (int i = 0; i < 32; i += 8)
        tile[ty + i][tx] = src[(size_t)(k0 + ty + i) * N + nloc + tx];
    __syncthreads();
#pragma unroll
    for (int i = 0; i < 32; i += 8)
        dst[(size_t)(orow + ty + i) * Cc + k0 + tx] = __float2half(tile[tx][ty + i]);
}

// ============================================================
// GEMM common: 128 threads, 4 warps of 64x64 (CTA 128x128).
// K-chunk 64, 2-stage cp.async.
// ============================================================
#define SMH 72
#define STG_A (128 * SMH)
#define STAGE_H (2 * 128 * SMH)
#define GEMM_SMEM (2 * STAGE_H * 2)   // 73728 bytes

#define GEMM_ISSUE_DEF(Aptr, Bptr)                                             \
    auto issue = [&](int st, int kc) {                                         \
        __half* As = sh + st * STAGE_H;                                        \
        __half* Bs = As + STG_A;                                               \
        int r8 = tid >> 3;                                                     \
        int cl = (tid & 7) * 8;                                                \
        _Pragma("unroll") for (int i = 0; i < 8; i++) {                        \
            int row = i * 16 + r8;                                             \
            cpa16(&As[row * SMH + cl], Aptr + (size_t)(bm + row) * 1024 + kc + cl); \
            cpa16(&Bs[row * SMH + cl], Bptr + (size_t)(bn + row) * 1024 + kc + cl); \
        }                                                                      \
        CP_COMMIT();                                                           \
    };

// plain (R15) mainloop: frag loads inline per ks. Low regs -> (128,3).
#define GEMM_MAINLOOP_PLAIN(Aptr, Bptr)                                        \
    float acc[4][8][4];                                                        \
    _Pragma("unroll") for (int mt = 0; mt < 4; mt++)                           \
    _Pragma("unroll") for (int nt = 0; nt < 8; nt++)                           \
    _Pragma("unroll") for (int i = 0; i < 4; i++) acc[mt][nt][i] = 0.f;        \
    GEMM_ISSUE_DEF(Aptr, Bptr)                                                 \
    issue(0, 0);                                                               \
    for (int c = 0; c < 16; c++) {                                             \
        CP_WAIT(0);                                                            \
        __syncthreads();                                                       \
        if (c + 1 < 16) issue((c + 1) & 1, (c + 1) * 64);                      \
        uint32_t As_u = sh_u + (c & 1) * STAGE_H * 2;                          \
        uint32_t Bs_u = As_u + STG_A * 2;                                      \
        _Pragma("unroll") for (int ks = 0; ks < 4; ks++) {                     \
            int k0 = ks * 16;                                                  \
            uint32_t am[4][4], bmx[4][4];                                      \
            _Pragma("unroll") for (int mt = 0; mt < 4; mt++)                   \
                ldmx4(am[mt], As_u + 2 * ((m0 + mt * 16 + aro) * SMH + k0 + aco)); \
            _Pragma("unroll") for (int p = 0; p < 4; p++)                      \
                ldmx4(bmx[p], Bs_u + 2 * ((n0 + p * 16 + bro) * SMH + k0 + bco)); \
            _Pragma("unroll") for (int mt = 0; mt < 4; mt++)                   \
            _Pragma("unroll") for (int p = 0; p < 4; p++) {                    \
                mma16816(acc[mt][2 * p],     am[mt][0], am[mt][1], am[mt][2], am[mt][3], \
                         bmx[p][0], bmx[p][1]);                                \
                mma16816(acc[mt][2 * p + 1], am[mt][0], am[mt][1], am[mt][2], am[mt][3], \
                         bmx[p][2], bmx[p][3]);                                \
            }                                                                  \
        }                                                                      \
    }

// frag-pipelined (R16) mainloop: high regs -> (128,2), for grids <= 296.
#define GEMM_MAINLOOP_PIPE(Aptr, Bptr)                                         \
    float acc[4][8][4];                                                        \
    _Pragma("unroll") for (int mt = 0; mt < 4; mt++)                           \
    _Pragma("unroll") for (int nt = 0; nt < 8; nt++)                           \
    _Pragma("unroll") for (int i = 0; i < 4; i++) acc[mt][nt][i] = 0.f;        \
    GEMM_ISSUE_DEF(Aptr, Bptr)                                                 \
    uint32_t am[2][4][4], bmx[2][4][4];                                        \
    auto ldfr = [&](uint32_t base_u, int fb, int k0) {                         \
        uint32_t As_u = base_u;                                                \
        uint32_t Bs_u = base_u + STG_A * 2;                                    \
        _Pragma("unroll") for (int mt = 0; mt < 4; mt++)                       \
            ldmx4(am[fb][mt], As_u + 2 * ((m0 + mt * 16 + aro) * SMH + k0 + aco)); \
        _Pragma("unroll") for (int p = 0; p < 4; p++)                          \
            ldmx4(bmx[fb][p], Bs_u + 2 * ((n0 + p * 16 + bro) * SMH + k0 + bco)); \
    };                                                                         \
    issue(0, 0);                                                               \
    for (int c = 0; c < 16; c++) {                                             \
        CP_WAIT(0);                                                            \
        __syncthreads();                                                       \
        uint32_t base_u = sh_u + (c & 1) * STAGE_H * 2;                        \
        ldfr(base_u, 0, 0);                                                    \
        if (c + 1 < 16) issue((c + 1) & 1, (c + 1) * 64);                      \
        _Pragma("unroll") for (int ks = 0; ks < 4; ks++) {                     \
            if (ks < 3) ldfr(base_u, (ks + 1) & 1, (ks + 1) * 16);             \
            int rb = ks & 1;                                                   \
            _Pragma("unroll") for (int mt = 0; mt < 4; mt++)                   \
            _Pragma("unroll") for (int p = 0; p < 4; p++) {                    \
                mma16816(acc[mt][2 * p],                                       \
                         am[rb][mt][0], am[rb][mt][1], am[rb][mt][2], am[rb][mt][3], \
                         bmx[rb][p][0], bmx[rb][p][1]);                        \
                mma16816(acc[mt][2 * p + 1],                                   \
                         am[rb][mt][0], am[rb][mt][1], am[rb][mt][2], am[rb][mt][3], \
                         bmx[rb][p][2], bmx[rb][p][3]);                        \
            }                                                                  \
        }                                                                      \
    }

#define GEMM_PROLOG                                                            \
    extern __shared__ __half sh[];                                             \
    int tid = threadIdx.x, wid = tid >> 5, lane = tid & 31;                    \
    int gr = lane >> 2, gc = lane & 3;                                         \
    int bm = blockIdx.y * 128, bn = blockIdx.x * 128;                          \
    int m0 = (wid & 1) * 64, n0 = (wid >> 1) * 64;                             \
    const int aro = ((lane & 8) ? 8 : 0) + (lane & 7);                         \
    const int aco = (lane & 16) ? 8 : 0;                                       \
    const int bro = ((lane & 16) ? 8 : 0) + (lane & 7);                        \
    const int bco = (lane & 8) ? 8 : 0;                                        \
    const uint32_t sh_u = (uint32_t)__cvta_generic_to_shared(sh);

// ============================================================
// QKV GEMM (plain loop, 3 CTAs/SM, single wave for 384 CTAs)
// ============================================================
__global__ __launch_bounds__(128, 3) void gemm_qkv(
    const __half* __restrict__ A, const __half* __restrict__ BT,
    __half* __restrict__ Og,
    const float* __restrict__ cosp, const float* __restrict__ sinp)
{
    GEMM_PROLOG
    GEMM_MAINLOOP_PLAIN(A, BT)

    int ntile = blockIdx.x;
    int hb = bn + n0;

    if (ntile >= 10) {
#pragma unroll
        for (int mt = 0; mt < 4; mt++)
#pragma unroll
            for (int nt = 0; nt < 8; nt++) {
                int row = bm + m0 + mt * 16 + gr;
                int col = hb + nt * 8 + 2 * gc;
                *(__half2*)&Og[(size_t)row * QKVN + col] =
                    __floats2half2_rn(acc[mt][nt][0], acc[mt][nt][1]);
                *(__half2*)&Og[(size_t)(row + 8) * QKVN + col] =
                    __floats2half2_rn(acc[mt][nt][2], acc[mt][nt][3]);
            }
        return;
    }

    float scl = (ntile < 8) ? QSCALE : 1.0f;
#pragma unroll
    for (int mt = 0; mt < 4; mt++) {
#pragma unroll
        for (int j = 0; j < 2; j++) {
            int row = bm + m0 + mt * 16 + gr + j * 8;
            int t = row & (Tt - 1);
            float o1a[4][2], o2a[4][2];
            float ss = 0.f;
#pragma unroll
            for (int nt = 0; nt < 4; nt++) {
                int d = nt * 8 + 2 * gc;
                float2 c2 = *(const float2*)&cosp[t * 32 + d];
                float2 s2 = *(const float2*)&sinp[t * 32 + d];
#pragma unroll
                for (int i = 0; i < 2; i++) {
                    float cv = i ? c2.y : c2.x;
                    float sv = i ? s2.y : s2.x;
                    float x1 = acc[mt][nt][j * 2 + i];
                    float x2 = acc[mt][nt + 4][j * 2 + i];
                    float o1 = x1 * cv + x2 * sv;
                    float o2 = -x1 * sv + x2 * cv;
                    o1a[nt][i] = o1;
                    o2a[nt][i] = o2;
                    ss += o1 * o1 + o2 * o2;
                }
            }
            ss += __shfl_xor_sync(0xffffffffu, ss, 1);
            ss += __shfl_xor_sync(0xffffffffu, ss, 2);
            float inv = rsqrtf(ss * (1.0f / HDim) + 1e-6f) * scl;

            __half* og = Og + (size_t)row * QKVN + hb;
#pragma unroll
            for (int nt = 0; nt < 4; nt++) {
                int d = nt * 8 + 2 * gc;
                *(__half2*)&og[d] =
                    __floats2half2_rn(o1a[nt][0] * inv, o1a[nt][1] * inv);
                *(__half2*)&og[d + 32] =
                    __floats2half2_rn(o2a[nt][0] * inv, o2a[nt][1] * inv);
            }
        }
    }
}

// ============================================================
// Wo GEMM (frag-pipelined loop, 256 CTAs fit one wave at 2/SM)
// ============================================================
__global__ __launch_bounds__(128, 2) void gemm_wo(
    const __half* __restrict__ A, const __half* __restrict__ BT,
    float* __restrict__ C)
{
    GEMM_PROLOG
    GEMM_MAINLOOP_PIPE(A, BT)

#pragma unroll
    for (int mt = 0; mt < 4; mt++)
#pragma unroll
        for (int nt = 0; nt < 8; nt++) {
            int row = bm + m0 + mt * 16 + gr;
            int col = bn + n0 + nt * 8 + 2 * gc;
            *(float2*)&C[(size_t)row * Cc + col] =
                make_float2(acc[mt][nt][0], acc[mt][nt][1]);
            *(float2*)&C[(size_t)(row + 8) * Cc + col] =
                make_float2(acc[mt][nt][2], acc[mt][nt][3]);
        }
}

// ============================================================
// fp16 flash attention: 128 threads, 4 warps x 32 q-rows,
// register-resident P, double-buffered KV tiles AND
// double-buffered K/V fragments (hide ldmatrix latency).
// ============================================================
#define AST 72
#define QS_OFF 0
#define KS_OFF (128 * AST)
#define VS_OFF (KS_OFF + 2 * 64 * AST)
#define FLASH_SMEM ((128 * AST + 4 * 64 * AST) * 2)   // 55296 bytes

__global__ __launch_bounds__(128) void flash_attn_mma(
    const __half* __restrict__ QKV, __half* __restrict__ Og)
{
    extern __shared__ __half sm[];

    int qb = (gridDim.x - 1) - blockIdx.x;   // LPT: biggest first
    int h = blockIdx.y, b = blockIdx.z;
    int q0 = qb * 128;
    int kvh = h >> 2;
    int tid = threadIdx.x, wid = tid >> 5, lane = tid & 31;
    int gr = lane >> 2, gc = lane & 3;
    int m0 = wid * 32;
    const int aro = ((lane & 8) ? 8 : 0) + (lane & 7);
    const int aco = (lane & 16) ? 8 : 0;
    const int bro = ((lane & 16) ? 8 : 0) + (lane & 7);
    const int bco = (lane & 8) ? 8 : 0;

    const uint32_t sm_u = (uint32_t)__cvta_generic_to_shared(sm);
    const uint32_t Qs_u = sm_u + QS_OFF * 2;

    const __half* Qbase = QKV + (size_t)(b * Tt + q0) * QKVN + h * HDim;
    const __half* KVbase = QKV + (size_t)(b * Tt) * QKVN + 1024 + kvh * HDim;

#pragma unroll
    for (int i = 0; i < 8; i++) {
        int fi = i * 128 + tid;
        int row = fi >> 3, c8 = (fi & 7) * 8;
        cpa16(&sm[QS_OFF + row * AST + c8], Qbase + (size_t)row * QKVN + c8);
    }
    CP_COMMIT();

    auto issueKV = [&](int sbuf, int kt) {
        const __half* Kb = KVbase + (size_t)(kt * 64) * QKVN;
#pragma unroll
        for (int i = 0; i < 4; i++) {
            int fi = i * 128 + tid;
            int row = fi >> 3, c8 = (fi & 7) * 8;
            const __half* g = Kb + (size_t)row * QKVN + c8;
            cpa16(&sm[KS_OFF + sbuf * 64 * AST + row * AST + c8], g);
            cpa16(&sm[VS_OFF + sbuf * 64 * AST + row * AST + c8], g + 256);
        }
        CP_COMMIT();
    };

    issueKV(0, 0);
    CP_WAIT(1);
    __syncthreads();

    uint32_t qf[2][4][4];
#pragma unroll
    for (int mt = 0; mt < 2; mt++)
#pragma unroll
        for (int ks = 0; ks < 4; ks++)
            ldmx4(qf[mt][ks], Qs_u + 2 * ((m0 + mt * 16 + aro) * AST + ks * 16 + aco));

    float o[2][8][4];
#pragma unroll
    for (int mt = 0; mt < 2; mt++)
#pragma unroll
        for (int nt = 0; nt < 8; nt++)
#pragma unroll
            for (int i = 0; i < 4; i++) o[mt][nt][i] = 0.f;
    float mx[2][2], lsum[2][2];
#pragma unroll
    for (int mt = 0; mt < 2; mt++) {
        mx[mt][0] = -1e30f; mx[mt][1] = -1e30f;
        lsum[mt][0] = 0.f;  lsum[mt][1] = 0.f;
    }

    const int nkt = 2 * qb + 2;

    for (int kt = 0; kt < nkt; kt++) {
        int kv0 = kt * 64;
        int buf = kt & 1;
        CP_WAIT(0);
        __syncthreads();
        if (kt + 1 < nkt) issueKV(buf ^ 1, kt + 1);

        uint32_t Ks_u = sm_u + (KS_OFF + buf * 64 * AST) * 2;
        uint32_t Vs_u = sm_u + (VS_OFF + buf * 64 * AST) * 2;

        float s[2][8][4];
#pragma unroll
        for (int mt = 0; mt < 2; mt++)
#pragma unroll
            for (int nt = 0; nt < 8; nt++)
#pragma unroll
                for (int i = 0; i < 4; i++) s[mt][nt][i] = 0.f;

        // ---- S = Q K^T (frag-pipelined K loads) ----
        {
            uint32_t kf[2][4][4];
#pragma unroll
            for (int p = 0; p < 4; p++)
                ldmx4(kf[0][p], Ks_u + 2 * ((p * 16 + bro) * AST + bco));
#pragma unroll
            for (int ks = 0; ks < 4; ks++) {
                if (ks < 3) {
#pragma unroll
                    for (int p = 0; p < 4; p++)
                        ldmx4(kf[(ks + 1) & 1][p],
                              Ks_u + 2 * ((p * 16 + bro) * AST + (ks + 1) * 16 + bco));
                }
                int rb = ks & 1;
#pragma unroll
                for (int mt = 0; mt < 2; mt++)
#pragma unroll
                    for (int nt = 0; nt < 8; nt++) {
                        int p = nt >> 1, hh = nt & 1;
                        mma16816(s[mt][nt],
                                 qf[mt][ks][0], qf[mt][ks][1], qf[mt][ks][2], qf[mt][ks][3],
                                 kf[rb][p][2 * hh], kf[rb][p][2 * hh + 1]);
                    }
            }
        }

        if (kv0 + 63 > q0) {
#pragma unroll
            for (int mt = 0; mt < 2; mt++) {
                int rl = q0 + m0 + mt * 16 + gr;
                int rh = rl + 8;
#pragma unroll
                for (int nt = 0; nt < 8; nt++) {
                    int c0 = kv0 + nt * 8 + 2 * gc;
                    if (c0 > rl)     s[mt][nt][0] = -1e30f;
                    if (c0 + 1 > rl) s[mt][nt][1] = -1e30f;
                    if (c0 > rh)     s[mt][nt][2] = -1e30f;
                    if (c0 + 1 > rh) s[mt][nt][3] = -1e30f;
                }
            }
        }

        uint32_t pf[2][4][4];
#pragma unroll
        for (int mt = 0; mt < 2; mt++) {
            float tlo = -1e30f, thi = -1e30f;
#pragma unroll
            for (int nt = 0; nt < 8; nt++) {
                tlo = fmaxf(tlo, fmaxf(s[mt][nt][0], s[mt][nt][1]));
                thi = fmaxf(thi, fmaxf(s[mt][nt][2], s[mt][nt][3]));
            }
            tlo = fmaxf(tlo, __shfl_xor_sync(0xffffffffu, tlo, 1));
            tlo = fmaxf(tlo, __shfl_xor_sync(0xffffffffu, tlo, 2));
            thi = fmaxf(thi, __shfl_xor_sync(0xffffffffu, thi, 1));
            thi = fmaxf(thi, __shfl_xor_sync(0xffffffffu, thi, 2));

            float mn_lo = fmaxf(mx[mt][0], tlo);
            float mn_hi = fmaxf(mx[mt][1], thi);
            float cor_lo = ex2f(mx[mt][0] - mn_lo);
            float cor_hi = ex2f(mx[mt][1] - mn_hi);
            mx[mt][0] = mn_lo; mx[mt][1] = mn_hi;
            lsum[mt][0] *= cor_lo; lsum[mt][1] *= cor_hi;
#pragma unroll
            for (int nt = 0; nt < 8; nt++) {
                o[mt][nt][0] *= cor_lo; o[mt][nt][1] *= cor_lo;
                o[mt][nt][2] *= cor_hi; o[mt][nt][3] *= cor_hi;
            }

#pragma unroll
            for (int ks = 0; ks < 4; ks++) {
                float a0 = ex2f(s[mt][2 * ks][0] - mn_lo);
                float a1 = ex2f(s[mt][2 * ks][1] - mn_lo);
                float a2 = ex2f(s[mt][2 * ks][2] - mn_hi);
                float a3 = ex2f(s[mt][2 * ks][3] - mn_hi);
                float b0 = ex2f(s[mt][2 * ks + 1][0] - mn_lo);
                float b1 = ex2f(s[mt][2 * ks + 1][1] - mn_lo);
                float b2 = ex2f(s[mt][2 * ks + 1][2] - mn_hi);
                float b3 = ex2f(s[mt][2 * ks + 1][3] - mn_hi);
                lsum[mt][0] += a0 + a1 + b0 + b1;
                lsum[mt][1] += a2 + a3 + b2 + b3;
                pf[mt][ks][0] = packh2(a0, a1);
                pf[mt][ks][1] = packh2(a2, a3);
                pf[mt][ks][2] = packh2(b0, b1);
                pf[mt][ks][3] = packh2(b2, b3);
            }
        }

        // ---- O += P V (frag-pipelined V loads) ----
        {
            uint32_t vf[2][4][4];
#pragma unroll
            for (int p = 0; p < 4; p++)
                ldmx4t(vf[0][p], Vs_u + 2 * ((aro) * AST + p * 16 + aco));
#pragma unroll
            for (int ks = 0; ks < 4; ks++) {
                if (ks < 3) {
#pragma unroll
                    for (int p = 0; p < 4; p++)
                        ldmx4t(vf[(ks + 1) & 1][p],
                               Vs_u + 2 * (((ks + 1) * 16 + aro) * AST + p * 16 + aco));
                }
                int rb = ks & 1;
#pragma unroll
                for (int mt = 0; mt < 2; mt++)
#pragma unroll
                    for (int nt = 0; nt < 8; nt++) {
                        int p = nt >> 1, hh = nt & 1;
                        mma16816(o[mt][nt],
                                 pf[mt][ks][0], pf[mt][ks][1], pf[mt][ks][2], pf[mt][ks][3],
                                 vf[rb][p][2 * hh], vf[rb][p][2 * hh + 1]);
                    }
            }
        }
    }

    __half* Obase = Og + ((size_t)(b * Tt) * Hh + h) * HDim;
#pragma unroll
    for (int mt = 0; mt < 2; mt++) {
        float llo = lsum[mt][0], lhi = lsum[mt][1];
        llo += __shfl_xor_sync(0xffffffffu, llo, 1);
        llo += __shfl_xor_sync(0xffffffffu, llo, 2);
        lhi += __shfl_xor_sync(0xffffffffu, lhi, 1);
        lhi += __shfl_xor_sync(0xffffffffu, lhi, 2);
        float inv_lo = 1.f / llo;
        float inv_hi = 1.f / lhi;

        int row_lo = q0 + m0 + mt * 16 + gr;
        int row_hi = row_lo + 8;
#pragma unroll
        for (int nt = 0; nt < 8; nt++) {
            int col = nt * 8 + 2 * gc;
            *(__half2*)&Obase[(size_t)row_lo * (Hh * HDim) + col] =
                __floats2half2_rn(o[mt][nt][0] * inv_lo, o[mt][nt][1] * inv_lo);
            *(__half2*)&Obase[(size_t)row_hi * (Hh * HDim) + col] =
                __floats2half2_rn(o[mt][nt][2] * inv_hi, o[mt][nt][3] * inv_hi);
        }
    }
}

// ============================================================
// launch
// ============================================================
extern "C" void kernel_launch(void* const* d_in, const int* in_sizes, int n_in,
                              void* d_out, int out_size)
{
    const float* x  = (const float*)d_in[0];
    const float* cs = (const float*)d_in[1];
    const float* sn = (const float*)d_in[2];
    const float* Wq = (const float*)d_in[3];
    const float* Wk = (const float*)d_in[4];
    const float* Wv = (const float*)d_in[5];
    const float* Wo = (const float*)d_in[6];
    float* out = (float*)d_out;

    __half *Xh, *QKVh, *Yh, *WqkvTh, *WoTh;
    cudaGetSymbolAddress((void**)&Xh, g_Xh);
    cudaGetSymbolAddress((void**)&QKVh, g_QKVh);
    cudaGetSymbolAddress((void**)&Yh, g_Yh);
    cudaGetSymbolAddress((void**)&WqkvTh, g_WqkvTh);
    cudaGetSymbolAddress((void**)&WoTh, g_WoTh);

    cudaFuncSetAttribute(gemm_qkv,
                         cudaFuncAttributeMaxDynamicSharedMemorySize, GEMM_SMEM);
    cudaFuncSetAttribute(gemm_wo,
                         cudaFuncAttributeMaxDynamicSharedMemorySize, GEMM_SMEM);
    cudaFuncSetAttribute(flash_attn_mma,
                         cudaFuncAttributeMaxDynamicSharedMemorySize, FLASH_SMEM);

    const int M = Bsz * Tt;  // 4096

    // fused prep: x->fp16 + both weight transposes in one launch
    prep<<<PREP_GRID, 256>>>(x, Wq, Wk, Wv, Wo, Xh, WqkvTh, WoTh);

    // fused QKV projection + rope + rms -> fp16 (Q pre-scaled)
    gemm_qkv<<<dim3(QKVN / 128, M / 128), 128, GEMM_SMEM>>>(Xh, WqkvTh, QKVh, cs, sn);

    // causal GQA flash attention (register-resident P, piped frags)
    flash_attn_mma<<<dim3(Tt / 128, Hh, Bsz), 128, FLASH_SMEM>>>(QKVh, Yh);

    // output projection
    gemm_wo<<<dim3(Cc / 128, M / 128), 128, GEMM_SMEM>>>(Yh, WoTh, out);
}